// round 13
// baseline (speedup 1.0000x reference)
#include <cuda_runtime.h>
#include <math.h>
#include <stdint.h>

// Problem constants
#define BB 32
#define TT 512
#define EE 256
#define HH 256
#define GG 1024          // 4*H
#define CC 20
#define MM (BB * TT)     // 16384

typedef unsigned long long ull;

// ---------------- f32x2 packed helpers (Blackwell) ----------------
__device__ __forceinline__ ull dup_f32(float x) {
    ull r;
    asm("mov.b64 %0, {%1, %1};" : "=l"(r) : "f"(x));
    return r;
}
__device__ __forceinline__ ull pack_f32(float lo, float hi) {
    ull r;
    asm("mov.b64 %0, {%1, %2};" : "=l"(r) : "f"(lo), "f"(hi));
    return r;
}
__device__ __forceinline__ void ffma2(ull& acc, ull a, ull b) {
    asm("fma.rn.f32x2 %0, %1, %2, %0;" : "+l"(acc) : "l"(a), "l"(b));
}
__device__ __forceinline__ float2 unpack_f32(ull v) {
    float lo, hi;
    asm("mov.b64 {%0, %1}, %2;" : "=f"(lo), "=f"(hi) : "l"(v));
    return make_float2(lo, hi);
}

// ---------------- cluster / DSMEM helpers ----------------
__device__ __forceinline__ uint32_t smem_u32(const void* p) {
    uint32_t a;
    asm("{ .reg .u64 t; cvta.to.shared.u64 t, %1; cvt.u32.u64 %0, t; }"
        : "=r"(a) : "l"(p));
    return a;
}
__device__ __forceinline__ void st_cluster_f32(uint32_t local_addr, uint32_t rank, float v) {
    uint32_t ra;
    asm("mapa.shared::cluster.u32 %0, %1, %2;" : "=r"(ra) : "r"(local_addr), "r"(rank));
    asm volatile("st.shared::cluster.f32 [%0], %1;" :: "r"(ra), "f"(v) : "memory");
}
__device__ __forceinline__ void mbar_init(uint32_t addr, uint32_t count) {
    asm volatile("mbarrier.init.shared.b64 [%0], %1;" :: "r"(addr), "r"(count) : "memory");
}
__device__ __forceinline__ void mbar_arrive_remote(uint32_t local_addr, uint32_t rank) {
    uint32_t ra;
    asm("mapa.shared::cluster.u32 %0, %1, %2;" : "=r"(ra) : "r"(local_addr), "r"(rank));
    asm volatile("mbarrier.arrive.release.cluster.shared::cluster.b64 _, [%0];"
                 :: "r"(ra) : "memory");
}
__device__ __forceinline__ void mbar_wait_parity_cluster(uint32_t addr, uint32_t parity) {
    uint32_t done;
    asm volatile(
        "{\n\t"
        ".reg .pred p;\n\t"
        "mbarrier.try_wait.parity.acquire.cluster.shared::cta.b64 p, [%1], %2;\n\t"
        "selp.b32 %0, 1, 0, p;\n\t"
        "}"
        : "=r"(done) : "r"(addr), "r"(parity) : "memory");
    if (!done) {
        asm volatile(
            "{\n\t"
            ".reg .pred P1;\n\t"
            "WAIT_LOOP_%=:\n\t"
            "mbarrier.try_wait.parity.acquire.cluster.shared::cta.b64 P1, [%0], %1, 0x989680;\n\t"
            "@P1 bra.uni WAIT_DONE_%=;\n\t"
            "bra.uni WAIT_LOOP_%=;\n\t"
            "WAIT_DONE_%=:\n\t"
            "}"
            :: "r"(addr), "r"(parity) : "memory");
    }
}
#define CLUSTER_SYNC_() do { \
    asm volatile("barrier.cluster.arrive.aligned;" ::: "memory"); \
    asm volatile("barrier.cluster.wait.aligned;" ::: "memory"); } while (0)

// ---------------- device scratch (allocation-free rule: static __device__) --------------
__device__ float g_xp_f[(size_t)MM * GG];   // 64 MB
__device__ float g_xp_b[(size_t)MM * GG];   // 64 MB
__device__ float g_out_f[(size_t)MM * HH];  // 16 MB
__device__ float g_out_b[(size_t)MM * HH];  // 16 MB
__device__ float g_logits[(size_t)MM * CC];
__device__ float g_llh[BB];

// scan bookkeeping
__device__ int g_perm[BB];                  // sorted(batch) -> original batch
__device__ int g_Lsorted[BB];               // lengths, descending

// GEMM compaction
__device__ int g_rows[MM];                  // packed (b<<16)|t for t < seq_len[b]
__device__ int g_nrows;

// ---------------- kernel 0: setup ----------------
__global__ __launch_bounds__(256)
void setup_kernel(const int* __restrict__ seq_len)
{
    __shared__ int off_s[BB + 1];
    int tid = threadIdx.x;

    if (tid == 0) {
        int L[BB], p[BB];
        for (int i = 0; i < BB; i++) { L[i] = seq_len[i]; p[i] = i; }
        // stable insertion sort, descending by L
        for (int i = 1; i < BB; i++) {
            int kl = L[i], kp = p[i];
            int j = i - 1;
            while (j >= 0 && L[j] < kl) { L[j + 1] = L[j]; p[j + 1] = p[j]; j--; }
            L[j + 1] = kl; p[j + 1] = kp;
        }
        for (int i = 0; i < BB; i++) { g_perm[i] = p[i]; g_Lsorted[i] = L[i]; }
        // prefix offsets in ORIGINAL batch order for row compaction
        int off = 0;
        for (int b = 0; b < BB; b++) { off_s[b] = off; off += seq_len[b]; }
        off_s[BB] = off;
        g_nrows = off;
    }
    __syncthreads();

    // fill compacted row list: thread group (b, r) writes rows t = r, r+8, ...
    int b = tid >> 3, r = tid & 7;
    int off = off_s[b];
    int L = off_s[b + 1] - off;
    for (int t = r; t < L; t += 8)
        g_rows[off + t] = (b << 16) | t;
}

// ---------------- kernel 1: xp = gather(emb, x[, reversed]) @ Wih^T + bias -------------
// Both directions in ONE launch (blockIdx.z = rev). Compacted M (only t < seq_len rows).
// Tile 128x128, BK=8, 256 threads, 8x8 per thread, f32x2 packed FMA inner loop.
__global__ __launch_bounds__(256)
void gemm_xp(const int* __restrict__ x, const int* __restrict__ seq_len,
             const float* __restrict__ emb,
             const float* __restrict__ Wih_f, const float* __restrict__ b_f,
             const float* __restrict__ Wih_b, const float* __restrict__ b_b)
{
    const int BM = 128, BN = 128, BK = 8;
    __shared__ float As[BK][BM];
    __shared__ float Bs[BK][BN];
    __shared__ int tok[BM];
    __shared__ int orow[BM];

    int nrows = g_nrows;
    int m0 = blockIdx.y * BM;
    if (m0 >= nrows) return;

    int rev = blockIdx.z;
    const float* __restrict__ Wih  = rev ? Wih_b : Wih_f;
    const float* __restrict__ bias = rev ? b_b   : b_f;
    float* __restrict__ xp         = rev ? g_xp_b : g_xp_f;

    int tid = threadIdx.x;                 // 256
    int n0 = blockIdx.x * BN;

    if (tid < BM) {
        int m = m0 + tid;
        if (m < nrows) {
            int pk = g_rows[m];
            int b = pk >> 16, t = pk & 0xFFFF;
            int tp = rev ? (seq_len[b] - 1 - t) : t;   // t < L by construction
            tok[tid]  = x[b * TT + tp];
            orow[tid] = b * TT + t;
        } else {
            tok[tid] = 0;
            orow[tid] = -1;
        }
    }
    __syncthreads();

    int tx = tid & 15, ty = tid >> 4;
    int am = tid >> 1, ak = (tid & 1) * 4;
    int bn = tid >> 1, bk = (tid & 1) * 4;

    ull acc2[8][4];
#pragma unroll
    for (int i = 0; i < 8; i++)
#pragma unroll
        for (int j = 0; j < 4; j++) acc2[i][j] = 0ull;

    for (int k0 = 0; k0 < EE; k0 += BK) {
        float4 av = *reinterpret_cast<const float4*>(
            &emb[(size_t)tok[am] * EE + k0 + ak]);
        float4 bv = *reinterpret_cast<const float4*>(
            &Wih[(size_t)(n0 + bn) * EE + k0 + bk]);
        __syncthreads();   // previous tile fully consumed
        As[ak + 0][am] = av.x; As[ak + 1][am] = av.y;
        As[ak + 2][am] = av.z; As[ak + 3][am] = av.w;
        Bs[bk + 0][bn] = bv.x; Bs[bk + 1][bn] = bv.y;
        Bs[bk + 2][bn] = bv.z; Bs[bk + 3][bn] = bv.w;
        __syncthreads();

#pragma unroll
        for (int kk = 0; kk < BK; kk++) {
            float a[8], b[8];
            *reinterpret_cast<float4*>(&a[0]) =
                *reinterpret_cast<const float4*>(&As[kk][ty * 8]);
            *reinterpret_cast<float4*>(&a[4]) =
                *reinterpret_cast<const float4*>(&As[kk][ty * 8 + 4]);
            *reinterpret_cast<float4*>(&b[0]) =
                *reinterpret_cast<const float4*>(&Bs[kk][tx * 8]);
            *reinterpret_cast<float4*>(&b[4]) =
                *reinterpret_cast<const float4*>(&Bs[kk][tx * 8 + 4]);
            ull bp[4];
#pragma unroll
            for (int j = 0; j < 4; j++) bp[j] = pack_f32(b[2 * j], b[2 * j + 1]);
#pragma unroll
            for (int i = 0; i < 8; i++) {
                ull ai = dup_f32(a[i]);
#pragma unroll
                for (int j = 0; j < 4; j++) ffma2(acc2[i][j], ai, bp[j]);
            }
        }
    }

    float bj[8];
#pragma unroll
    for (int j = 0; j < 8; j++) bj[j] = bias[n0 + tx * 8 + j];
#pragma unroll
    for (int i = 0; i < 8; i++) {
        int om = orow[ty * 8 + i];
        if (om >= 0) {
            size_t row = (size_t)om * GG + n0 + tx * 8;
            float2 p0 = unpack_f32(acc2[i][0]);
            float2 p1 = unpack_f32(acc2[i][1]);
            float2 p2 = unpack_f32(acc2[i][2]);
            float2 p3 = unpack_f32(acc2[i][3]);
            float4 v0, v1;
            v0.x = p0.x + bj[0]; v0.y = p0.y + bj[1];
            v0.z = p1.x + bj[2]; v0.w = p1.y + bj[3];
            v1.x = p2.x + bj[4]; v1.y = p2.y + bj[5];
            v1.z = p3.x + bj[6]; v1.w = p3.y + bj[7];
            *reinterpret_cast<float4*>(&xp[row]) = v0;
            *reinterpret_cast<float4*>(&xp[row + 4]) = v1;
        }
    }
}

// ---------------- kernel 2: clustered LSTM scan (DSMEM h-exchange, mbarrier sync) ------
// 128 CTAs = 16 clusters x 8. cluster cid: dir = cid&1, grp = cid>>1 (4 sorted batches).
// CTA rank owns hidden units [rank*32, rank*32+32) -> 128 gate rows of Whh (128KB) in
// SMEM, gate-contiguous layout lrow = u*4+q. Per step: 128row x 4batch x 256k micro-GEMM
// from SMEM, reduce via LDS128, cell update, h pushed to all 8 CTAs via
// st.shared::cluster, then mbarrier sync: 8 remote release-arrives, local acquire-wait.
__global__ __launch_bounds__(256) __cluster_dims__(8, 1, 1)
void lstm_scan4(const float* __restrict__ Whh_f, const float* __restrict__ Whh_b)
{
    extern __shared__ float sm[];
    float* Ws   = sm;                       // [256][128]  Ws[k*128 + u*4 + q]
    float* hs0  = sm + 256 * 128;           // [256][4]    h buffer parity 0
    float* hs1  = hs0 + 256 * 4;            // [256][4]    h buffer parity 1
    float* pbuf = hs1 + 256 * 4;            // [8][4][128] pbuf[(s*4+b)*128 + u*4+q]

    __shared__ __align__(8) ull mbar_sto;
    __shared__ int perm_s[4];
    __shared__ int Ls_s[4];

    int bid  = blockIdx.x;
    int cid  = bid >> 3;
    int rank = bid & 7;
    int dir  = cid & 1;
    int grp  = cid >> 1;
    int tid  = threadIdx.x;

    const float* __restrict__ xp  = dir ? g_xp_b : g_xp_f;
    const float* __restrict__ Whh = dir ? Whh_b : Whh_f;
    float* __restrict__ out       = dir ? g_out_b : g_out_f;

    uint32_t mbar_a = smem_u32(&mbar_sto);
    if (tid == 0) mbar_init(mbar_a, 8);
    if (tid < 4) {
        perm_s[tid] = g_perm[grp * 4 + tid];
        Ls_s[tid]   = g_Lsorted[grp * 4 + tid];
    }
    int Lmax = g_Lsorted[grp * 4];          // group sorted desc -> first is longest

    // ---- load this CTA's 128 gate rows of Whh into SMEM, gate-contiguous k-major ----
    for (int i = tid; i < 128 * 64; i += 256) {
        int lrow = i & 127, k4 = i >> 7;
        int u = lrow >> 2, q = lrow & 3;
        int grow = q * 256 + rank * 32 + u;
        float4 w = *reinterpret_cast<const float4*>(&Whh[(size_t)grow * 256 + k4 * 4]);
        Ws[(k4 * 4 + 0) * 128 + lrow] = w.x;
        Ws[(k4 * 4 + 1) * 128 + lrow] = w.y;
        Ws[(k4 * 4 + 2) * 128 + lrow] = w.z;
        Ws[(k4 * 4 + 3) * 128 + lrow] = w.w;
    }
    __syncthreads();
    CLUSTER_SYNC_();   // all SMEM + mbarrier inits visible before any pushes/arrives

    // GEMM roles: s = k-slice (8 x 32k), rowg = 4-row group (32) = unit index
    int s    = tid >> 5;
    int rowg = tid & 31;
    // cell roles (tid < 128): b_cell 0..3 (warp), u_cell 0..31 (lane)
    int b_cell = tid >> 5;
    int u_cell = tid & 31;
    int j_cell = rank * 32 + u_cell;

    uint32_t hs0_a = smem_u32(hs0);
    uint32_t hs1_a = smem_u32(hs1);

    const float4* W4 = reinterpret_cast<const float4*>(Ws);
    float4* P4 = reinterpret_cast<float4*>(pbuf);

    float c_state = 0.f;

    for (int t = 0; t < Lmax; t++) {
        int pr = t & 1;
        const float4* H4 = reinterpret_cast<const float4*>(pr ? hs1 : hs0);
        uint32_t hsw_a = pr ? hs0_a : hs1_a;   // write opposite parity

        // ---- prefetch xp gate values (cell threads) ----
        bool cellth = tid < 128;
        bool act = false;
        int ob = 0;
        float xg0 = 0.f, xg1 = 0.f, xg2 = 0.f, xg3 = 0.f;
        if (cellth) {
            act = (t < Ls_s[b_cell]);
            if (act) {
                ob = perm_s[b_cell];
                size_t xb = ((size_t)ob * TT + t) * GG + (size_t)rank * 32 + u_cell;
                xg0 = xp[xb];
                xg1 = xp[xb + 256];
                xg2 = xp[xb + 512];
                xg3 = xp[xb + 768];
            }
        }

        // ---- micro-GEMM over k-slice s (32 k), unit rowg's 4 gates, all 4 batches ----
        if (t > 0) {
            ull acc2[4][2];
#pragma unroll
            for (int i = 0; i < 4; i++) { acc2[i][0] = 0ull; acc2[i][1] = 0ull; }
            int kbase = s * 32;
#pragma unroll 8
            for (int k = 0; k < 32; k++) {
                float4 wv = W4[(kbase + k) * 32 + rowg];
                float4 hv = H4[kbase + k];
                ull w01 = pack_f32(wv.x, wv.y);
                ull w23 = pack_f32(wv.z, wv.w);
                ull hb;
                hb = dup_f32(hv.x); ffma2(acc2[0][0], w01, hb); ffma2(acc2[0][1], w23, hb);
                hb = dup_f32(hv.y); ffma2(acc2[1][0], w01, hb); ffma2(acc2[1][1], w23, hb);
                hb = dup_f32(hv.z); ffma2(acc2[2][0], w01, hb); ffma2(acc2[2][1], w23, hb);
                hb = dup_f32(hv.w); ffma2(acc2[3][0], w01, hb); ffma2(acc2[3][1], w23, hb);
            }
#pragma unroll
            for (int b = 0; b < 4; b++) {
                float2 p0 = unpack_f32(acc2[b][0]);
                float2 p1 = unpack_f32(acc2[b][1]);
                float4 v; v.x = p0.x; v.y = p0.y; v.z = p1.x; v.w = p1.y;
                P4[(s * 4 + b) * 32 + rowg] = v;
            }
        }
        __syncthreads();

        // ---- reduce 8 k-slices (LDS128) + cell update + DSMEM push ----
        if (cellth && act) {
            float g0 = xg0, g1 = xg1, g2 = xg2, g3 = xg3;
            if (t > 0) {
#pragma unroll
                for (int s2 = 0; s2 < 8; s2++) {
                    float4 v = P4[(s2 * 4 + b_cell) * 32 + u_cell];
                    g0 += v.x; g1 += v.y; g2 += v.z; g3 += v.w;
                }
            }
            float i_ = 1.f / (1.f + __expf(-g0));
            float f_ = 1.f / (1.f + __expf(-g1));
            float o_ = 1.f / (1.f + __expf(-g3));
            c_state = f_ * c_state + i_ * tanhf(g2);
            float hv = o_ * tanhf(c_state);

            uint32_t off = hsw_a + (uint32_t)(j_cell * 4 + b_cell) * 4u;
#pragma unroll
            for (int r = 0; r < 8; r++) st_cluster_f32(off, r, hv);

            out[((size_t)ob * TT + t) * HH + j_cell] = hv;
        }

        // ---- mbarrier cluster sync: 8 remote release-arrives, local acquire-wait ----
        __syncthreads();                 // all this CTA's pushes issued before arrive
        if (tid == 0) {
#pragma unroll
            for (int r = 0; r < 8; r++) mbar_arrive_remote(mbar_a, (uint32_t)r);
        }
        mbar_wait_parity_cluster(mbar_a, (uint32_t)(t & 1));
    }

    CLUSTER_SYNC_();   // teardown safety: no CTA exits while peers may still deliver
}

// ---------------- kernel 3: logits = log_softmax(concat(out_f, rev(out_b)) @ W_fc^T) ---
__global__ __launch_bounds__(256)
void logits_kernel(const int* __restrict__ seq_len,
                   const float* __restrict__ W_fc)
{
    int bt = blockIdx.x;
    int b = bt / TT, t = bt % TT;
    int L = seq_len[b];
    if (t >= L) return;

    __shared__ float outs[2 * HH];
    __shared__ float dots[CC];
    __shared__ float lse_s;

    int tid = threadIdx.x;  // 256
    outs[tid]       = g_out_f[(size_t)bt * HH + tid];
    outs[HH + tid]  = g_out_b[(size_t)(b * TT + (L - 1 - t)) * HH + tid];
    __syncthreads();

    int warp = tid >> 5, lane = tid & 31;
    for (int cls = warp; cls < CC; cls += 8) {
        float acc = 0.f;
#pragma unroll 4
        for (int e = lane; e < 2 * HH; e += 32)
            acc += outs[e] * W_fc[cls * (2 * HH) + e];
#pragma unroll
        for (int off = 16; off; off >>= 1)
            acc += __shfl_down_sync(0xffffffffu, acc, off);
        if (lane == 0) dots[cls] = acc;
    }
    __syncthreads();

    if (tid == 0) {
        float m = -INFINITY;
        for (int cI = 0; cI < CC; cI++) m = fmaxf(m, dots[cI]);
        float sum = 0.f;
        for (int cI = 0; cI < CC; cI++) sum += expf(dots[cI] - m);
        lse_s = m + logf(sum);
    }
    __syncthreads();

    if (tid < CC) g_logits[(size_t)bt * CC + tid] = dots[tid] - lse_s;
}

// ---------------- kernel 4: CRF gold score + forward algorithm, warp per batch ----------
__global__ __launch_bounds__(32)
void crf_kernel(const int* __restrict__ seq_len, const int* __restrict__ y,
                const float* __restrict__ start_t, const float* __restrict__ end_t,
                const float* __restrict__ trans)
{
    int b = blockIdx.x;
    int lane = threadIdx.x;  // 32

    __shared__ float trans_s[CC * CC];
    __shared__ float alpha_s[CC];
    for (int i = lane; i < CC * CC; i += 32) trans_s[i] = trans[i];
    __syncwarp();

    int L = seq_len[b];
    const float* lg = g_logits + (size_t)b * TT * CC;
    const int* yb = y + b * TT;

    float part = 0.f;
    for (int t = 1 + lane; t < L; t += 32)
        part += trans_s[yb[t - 1] * CC + yb[t]] + lg[t * CC + yb[t]];
#pragma unroll
    for (int off = 16; off; off >>= 1)
        part += __shfl_down_sync(0xffffffffu, part, off);

    float score = 0.f;
    if (lane == 0)
        score = part + start_t[yb[0]] + lg[yb[0]] + end_t[yb[L - 1]];

    int j = lane;
    float alpha = (j < CC) ? (start_t[j] + lg[j]) : -INFINITY;
    for (int t = 1; t < L; t++) {
        if (j < CC) alpha_s[j] = alpha;
        __syncwarp();
        float na = alpha;
        if (j < CC) {
            float m = -INFINITY;
#pragma unroll
            for (int i = 0; i < CC; i++)
                m = fmaxf(m, alpha_s[i] + trans_s[i * CC + j]);
            float sum = 0.f;
#pragma unroll
            for (int i = 0; i < CC; i++)
                sum += expf(alpha_s[i] + trans_s[i * CC + j] - m);
            na = m + logf(sum) + lg[t * CC + j];
        }
        __syncwarp();
        alpha = na;
    }

    if (j < CC) alpha_s[j] = alpha + end_t[j];
    __syncwarp();
    if (lane == 0) {
        float m = -INFINITY;
        for (int i = 0; i < CC; i++) m = fmaxf(m, alpha_s[i]);
        float sum = 0.f;
        for (int i = 0; i < CC; i++) sum += expf(alpha_s[i] - m);
        float logZ = m + logf(sum);
        g_llh[b] = score - logZ;
    }
}

// ---------------- kernel 5: loss = -sum_b llh[b] ----------------
__global__ __launch_bounds__(32)
void finalize_kernel(float* __restrict__ out)
{
    int lane = threadIdx.x;
    float v = g_llh[lane];
#pragma unroll
    for (int off = 16; off; off >>= 1)
        v += __shfl_down_sync(0xffffffffu, v, off);
    if (lane == 0) out[0] = -v;
}

// ---------------- launch ----------------
extern "C" void kernel_launch(void* const* d_in, const int* in_sizes, int n_in,
                              void* d_out, int out_size)
{
    (void)in_sizes; (void)n_in; (void)out_size;
    const int*   x       = (const int*)  d_in[0];
    const int*   seq_len = (const int*)  d_in[1];
    const int*   y       = (const int*)  d_in[2];
    // d_in[3] = mask (derived from seq_len instead)
    const float* emb     = (const float*)d_in[4];
    const float* Wih_f   = (const float*)d_in[5];
    const float* Whh_f   = (const float*)d_in[6];
    const float* b_f     = (const float*)d_in[7];
    const float* Wih_b   = (const float*)d_in[8];
    const float* Whh_b   = (const float*)d_in[9];
    const float* b_b     = (const float*)d_in[10];
    const float* W_fc    = (const float*)d_in[11];
    const float* start_t = (const float*)d_in[12];
    const float* end_t   = (const float*)d_in[13];
    const float* trans   = (const float*)d_in[14];
    float* out = (float*)d_out;

    // scan dynamic SMEM: Ws 128KB + hs 2x4KB + pbuf 16KB = 152KB
    const int scan_smem = (256 * 128 + 2 * 256 * 4 + 8 * 4 * 128) * (int)sizeof(float);
    static int smem_set = 0;
    if (!smem_set) {
        cudaFuncSetAttribute(lstm_scan4,
                             cudaFuncAttributeMaxDynamicSharedMemorySize, scan_smem);
        smem_set = 1;
    }

    setup_kernel<<<1, 256>>>(seq_len);

    dim3 ggrid(GG / 128, MM / 128, 2);
    gemm_xp<<<ggrid, 256>>>(x, seq_len, emb, Wih_f, b_f, Wih_b, b_b);

    lstm_scan4<<<128, 256, scan_smem>>>(Whh_f, Whh_b);

    logits_kernel<<<MM, 256>>>(seq_len, W_fc);

    crf_kernel<<<BB, 32>>>(seq_len, y, start_t, end_t, trans);

    finalize_kernel<<<1, 32>>>(out);
}

// round 14
// speedup vs baseline: 1.4015x; 1.4015x over previous
#include <cuda_runtime.h>
#include <math.h>
#include <stdint.h>

// Problem constants
#define BB 32
#define TT 512
#define EE 256
#define HH 256
#define GG 1024          // 4*H
#define CC 20
#define MM (BB * TT)     // 16384

typedef unsigned long long ull;

// ---------------- f32x2 packed helpers (Blackwell) ----------------
__device__ __forceinline__ ull dup_f32(float x) {
    ull r;
    asm("mov.b64 %0, {%1, %1};" : "=l"(r) : "f"(x));
    return r;
}
__device__ __forceinline__ ull pack_f32(float lo, float hi) {
    ull r;
    asm("mov.b64 %0, {%1, %2};" : "=l"(r) : "f"(lo), "f"(hi));
    return r;
}
__device__ __forceinline__ void ffma2(ull& acc, ull a, ull b) {
    asm("fma.rn.f32x2 %0, %1, %2, %0;" : "+l"(acc) : "l"(a), "l"(b));
}
__device__ __forceinline__ float2 unpack_f32(ull v) {
    float lo, hi;
    asm("mov.b64 {%0, %1}, %2;" : "=f"(lo), "=f"(hi) : "l"(v));
    return make_float2(lo, hi);
}

// ---------------- cluster / DSMEM helpers ----------------
__device__ __forceinline__ uint32_t smem_u32(const void* p) {
    uint32_t a;
    asm("{ .reg .u64 t; cvta.to.shared.u64 t, %1; cvt.u32.u64 %0, t; }"
        : "=r"(a) : "l"(p));
    return a;
}
__device__ __forceinline__ void st_cluster_v4(uint32_t local_addr, uint32_t rank, float4 v) {
    uint32_t ra;
    asm("mapa.shared::cluster.u32 %0, %1, %2;" : "=r"(ra) : "r"(local_addr), "r"(rank));
    asm volatile("st.shared::cluster.v4.f32 [%0], {%1, %2, %3, %4};"
                 :: "r"(ra), "f"(v.x), "f"(v.y), "f"(v.z), "f"(v.w) : "memory");
}
#define CLUSTER_SYNC_() do { \
    asm volatile("barrier.cluster.arrive.aligned;" ::: "memory"); \
    asm volatile("barrier.cluster.wait.aligned;" ::: "memory"); } while (0)

// ---------------- device scratch (allocation-free rule: static __device__) --------------
__device__ float g_xp_f[(size_t)MM * GG];   // 64 MB
__device__ float g_xp_b[(size_t)MM * GG];   // 64 MB
__device__ float g_out_f[(size_t)MM * HH];  // 16 MB
__device__ float g_out_b[(size_t)MM * HH];  // 16 MB
__device__ float g_logits[(size_t)MM * CC];
__device__ float g_llh[BB];

// scan bookkeeping
__device__ int g_perm[BB];                  // sorted(batch) -> original batch
__device__ int g_Lsorted[BB];               // lengths, descending

// GEMM compaction
__device__ int g_rows[MM];                  // packed (b<<16)|t for t < seq_len[b]
__device__ int g_nrows;

// ---------------- kernel 0: setup ----------------
__global__ __launch_bounds__(256)
void setup_kernel(const int* __restrict__ seq_len)
{
    __shared__ int off_s[BB + 1];
    int tid = threadIdx.x;

    if (tid == 0) {
        int L[BB], p[BB];
        for (int i = 0; i < BB; i++) { L[i] = seq_len[i]; p[i] = i; }
        // stable insertion sort, descending by L
        for (int i = 1; i < BB; i++) {
            int kl = L[i], kp = p[i];
            int j = i - 1;
            while (j >= 0 && L[j] < kl) { L[j + 1] = L[j]; p[j + 1] = p[j]; j--; }
            L[j + 1] = kl; p[j + 1] = kp;
        }
        for (int i = 0; i < BB; i++) { g_perm[i] = p[i]; g_Lsorted[i] = L[i]; }
        // prefix offsets in ORIGINAL batch order for row compaction
        int off = 0;
        for (int b = 0; b < BB; b++) { off_s[b] = off; off += seq_len[b]; }
        off_s[BB] = off;
        g_nrows = off;
    }
    __syncthreads();

    // fill compacted row list: thread group (b, r) writes rows t = r, r+8, ...
    int b = tid >> 3, r = tid & 7;
    int off = off_s[b];
    int L = off_s[b + 1] - off;
    for (int t = r; t < L; t += 8)
        g_rows[off + t] = (b << 16) | t;
}

// ---------------- kernel 1: xp = gather(emb, x[, reversed]) @ Wih^T + bias -------------
// Compacted M (only t < seq_len rows). Tile 128x128, BK=8, 256 threads, 8x8 per thread,
// f32x2 packed FMA inner loop.
__global__ __launch_bounds__(256)
void gemm_xp(const int* __restrict__ x, const int* __restrict__ seq_len,
             const float* __restrict__ emb, const float* __restrict__ Wih,
             const float* __restrict__ bias, int rev)
{
    const int BM = 128, BN = 128, BK = 8;
    __shared__ float As[BK][BM];
    __shared__ float Bs[BK][BN];
    __shared__ int tok[BM];
    __shared__ int orow[BM];

    int nrows = g_nrows;
    int m0 = blockIdx.y * BM;
    if (m0 >= nrows) return;

    float* __restrict__ xp = rev ? g_xp_b : g_xp_f;

    int tid = threadIdx.x;                 // 256
    int n0 = blockIdx.x * BN;

    if (tid < BM) {
        int m = m0 + tid;
        if (m < nrows) {
            int pk = g_rows[m];
            int b = pk >> 16, t = pk & 0xFFFF;
            int tp = rev ? (seq_len[b] - 1 - t) : t;   // t < L by construction
            tok[tid]  = x[b * TT + tp];
            orow[tid] = b * TT + t;
        } else {
            tok[tid] = 0;
            orow[tid] = -1;
        }
    }
    __syncthreads();

    int tx = tid & 15, ty = tid >> 4;
    int am = tid >> 1, ak = (tid & 1) * 4;
    int bn = tid >> 1, bk = (tid & 1) * 4;

    ull acc2[8][4];
#pragma unroll
    for (int i = 0; i < 8; i++)
#pragma unroll
        for (int j = 0; j < 4; j++) acc2[i][j] = 0ull;

    for (int k0 = 0; k0 < EE; k0 += BK) {
        float4 av = *reinterpret_cast<const float4*>(
            &emb[(size_t)tok[am] * EE + k0 + ak]);
        float4 bv = *reinterpret_cast<const float4*>(
            &Wih[(size_t)(n0 + bn) * EE + k0 + bk]);
        __syncthreads();   // previous tile fully consumed
        As[ak + 0][am] = av.x; As[ak + 1][am] = av.y;
        As[ak + 2][am] = av.z; As[ak + 3][am] = av.w;
        Bs[bk + 0][bn] = bv.x; Bs[bk + 1][bn] = bv.y;
        Bs[bk + 2][bn] = bv.z; Bs[bk + 3][bn] = bv.w;
        __syncthreads();

#pragma unroll
        for (int kk = 0; kk < BK; kk++) {
            float a[8], b[8];
            *reinterpret_cast<float4*>(&a[0]) =
                *reinterpret_cast<const float4*>(&As[kk][ty * 8]);
            *reinterpret_cast<float4*>(&a[4]) =
                *reinterpret_cast<const float4*>(&As[kk][ty * 8 + 4]);
            *reinterpret_cast<float4*>(&b[0]) =
                *reinterpret_cast<const float4*>(&Bs[kk][tx * 8]);
            *reinterpret_cast<float4*>(&b[4]) =
                *reinterpret_cast<const float4*>(&Bs[kk][tx * 8 + 4]);
            ull bp[4];
#pragma unroll
            for (int j = 0; j < 4; j++) bp[j] = pack_f32(b[2 * j], b[2 * j + 1]);
#pragma unroll
            for (int i = 0; i < 8; i++) {
                ull ai = dup_f32(a[i]);
#pragma unroll
                for (int j = 0; j < 4; j++) ffma2(acc2[i][j], ai, bp[j]);
            }
        }
    }

    float bj[8];
#pragma unroll
    for (int j = 0; j < 8; j++) bj[j] = bias[n0 + tx * 8 + j];
#pragma unroll
    for (int i = 0; i < 8; i++) {
        int om = orow[ty * 8 + i];
        if (om >= 0) {
            size_t row = (size_t)om * GG + n0 + tx * 8;
            float2 p0 = unpack_f32(acc2[i][0]);
            float2 p1 = unpack_f32(acc2[i][1]);
            float2 p2 = unpack_f32(acc2[i][2]);
            float2 p3 = unpack_f32(acc2[i][3]);
            float4 v0, v1;
            v0.x = p0.x + bj[0]; v0.y = p0.y + bj[1];
            v0.z = p1.x + bj[2]; v0.w = p1.y + bj[3];
            v1.x = p2.x + bj[4]; v1.y = p2.y + bj[5];
            v1.z = p3.x + bj[6]; v1.w = p3.y + bj[7];
            *reinterpret_cast<float4*>(&xp[row]) = v0;
            *reinterpret_cast<float4*>(&xp[row + 4]) = v1;
        }
    }
}

// ---------------- kernel 2: clustered LSTM scan (R10 structure + prefetch + v4 push) ----
// 128 CTAs = 16 clusters x 8. cluster cid: dir = cid&1, grp = cid>>1 (4 sorted batches).
// CTA rank owns hidden units [rank*32, rank*32+32) -> 128 gate rows of Whh (128KB) in
// SMEM for the whole scan. Per step: 128row x 4batch x 256k micro-GEMM from SMEM,
// cell update into a staging buffer, ONE float4 remote store per thread (8 ranks x 32
// rows of 16B), ONE hardware cluster barrier. xp loads are software double-buffered
// one step ahead so DRAM latency never sits on the barrier-to-barrier critical path.
__global__ __launch_bounds__(256) __cluster_dims__(8, 1, 1)
void lstm_scan4(const float* __restrict__ Whh_f, const float* __restrict__ Whh_b)
{
    extern __shared__ float sm[];
    float* Ws   = sm;                       // [256][128]  Ws[k*128 + lrow], lrow = q*32+u
    float* hs0  = sm + 256 * 128;           // [256][4]    h buffer parity 0
    float* hs1  = hs0 + 256 * 4;            // [256][4]    h buffer parity 1
    float* pbuf = hs1 + 256 * 4;            // [8][128][4] pbuf[(s*128+row)*4 + b]

    __shared__ float4 stg4[32];             // staged h: stg4[u] = (b0,b1,b2,b3)
    __shared__ int perm_s[4];
    __shared__ int Ls_s[4];

    int bid  = blockIdx.x;
    int cid  = bid >> 3;
    int rank = bid & 7;
    int dir  = cid & 1;
    int grp  = cid >> 1;
    int tid  = threadIdx.x;

    const float* __restrict__ xp  = dir ? g_xp_b : g_xp_f;
    const float* __restrict__ Whh = dir ? Whh_b : Whh_f;
    float* __restrict__ out       = dir ? g_out_b : g_out_f;

    if (tid < 4) {
        perm_s[tid] = g_perm[grp * 4 + tid];
        Ls_s[tid]   = g_Lsorted[grp * 4 + tid];
    }
    int Lmax = g_Lsorted[grp * 4];          // group sorted desc -> first is longest

    // ---- load this CTA's 128 gate rows of Whh into SMEM, k-major ----
    for (int i = tid; i < 128 * 64; i += 256) {
        int lrow = i & 127, k4 = i >> 7;
        int q = lrow >> 5, u = lrow & 31;
        int grow = q * 256 + rank * 32 + u;
        float4 w = *reinterpret_cast<const float4*>(&Whh[(size_t)grow * 256 + k4 * 4]);
        Ws[(k4 * 4 + 0) * 128 + lrow] = w.x;
        Ws[(k4 * 4 + 1) * 128 + lrow] = w.y;
        Ws[(k4 * 4 + 2) * 128 + lrow] = w.z;
        Ws[(k4 * 4 + 3) * 128 + lrow] = w.w;
    }
    __syncthreads();
    CLUSTER_SYNC_();   // all SMEM ready before any DSMEM pushes

    // GEMM roles: s = k-slice (8 x 32k), rowg = 4-row group (32)
    int s    = tid >> 5;
    int rowg = tid & 31;
    // cell roles (tid < 128): b_cell 0..3, u_cell 0..31
    int b_cell = tid >> 5;
    int u_cell = tid & 31;
    int j_cell = rank * 32 + u_cell;

    uint32_t hs0_a = smem_u32(hs0);
    uint32_t hs1_a = smem_u32(hs1);

    const float4* W4 = reinterpret_cast<const float4*>(Ws);
    float4* P4 = reinterpret_cast<float4*>(pbuf);
    float* stg = reinterpret_cast<float*>(stg4);

    float c_state = 0.f;
    bool cellth = tid < 128;
    int ob = cellth ? perm_s[b_cell] : 0;

    // ---- prologue: prefetch xp gate values for t = 0 (all batches have L >= 1) ----
    bool act = cellth;
    float xg0 = 0.f, xg1 = 0.f, xg2 = 0.f, xg3 = 0.f;
    if (cellth) {
        size_t xb = (size_t)ob * TT * GG + (size_t)rank * 32 + u_cell;
        xg0 = xp[xb];
        xg1 = xp[xb + 256];
        xg2 = xp[xb + 512];
        xg3 = xp[xb + 768];
    }

    for (int t = 0; t < Lmax; t++) {
        int pr = t & 1;
        const float4* H4 = reinterpret_cast<const float4*>(pr ? hs1 : hs0);
        uint32_t hsw_a = pr ? hs0_a : hs1_a;   // write opposite parity

        // ---- issue prefetch for step t+1 (hidden under GEMM + barrier) ----
        bool act_n = cellth && (t + 1 < Ls_s[b_cell]);
        float ng0 = 0.f, ng1 = 0.f, ng2 = 0.f, ng3 = 0.f;
        if (act_n) {
            size_t xb = ((size_t)ob * TT + (t + 1)) * GG + (size_t)rank * 32 + u_cell;
            ng0 = xp[xb];
            ng1 = xp[xb + 256];
            ng2 = xp[xb + 512];
            ng3 = xp[xb + 768];
        }

        // ---- micro-GEMM over k-slice s (32 k), rows rowg*4..+4, all 4 batches ----
        if (t > 0) {
            ull acc2[4][2];
#pragma unroll
            for (int i = 0; i < 4; i++) { acc2[i][0] = 0ull; acc2[i][1] = 0ull; }
            int kbase = s * 32;
#pragma unroll 8
            for (int k = 0; k < 32; k++) {
                float4 wv = W4[(kbase + k) * 32 + rowg];
                float4 hv = H4[kbase + k];
                ull h01 = pack_f32(hv.x, hv.y);
                ull h23 = pack_f32(hv.z, hv.w);
                ull w;
                w = dup_f32(wv.x); ffma2(acc2[0][0], w, h01); ffma2(acc2[0][1], w, h23);
                w = dup_f32(wv.y); ffma2(acc2[1][0], w, h01); ffma2(acc2[1][1], w, h23);
                w = dup_f32(wv.z); ffma2(acc2[2][0], w, h01); ffma2(acc2[2][1], w, h23);
                w = dup_f32(wv.w); ffma2(acc2[3][0], w, h01); ffma2(acc2[3][1], w, h23);
            }
#pragma unroll
            for (int i = 0; i < 4; i++) {
                float2 p0 = unpack_f32(acc2[i][0]);
                float2 p1 = unpack_f32(acc2[i][1]);
                float4 v; v.x = p0.x; v.y = p0.y; v.z = p1.x; v.w = p1.y;
                P4[s * 128 + rowg * 4 + i] = v;
            }
        }
        __syncthreads();

        // ---- reduce 8 k-slices + cell update -> staging buffer + out ----
        if (act) {
            float g0 = xg0, g1 = xg1, g2 = xg2, g3 = xg3;
            if (t > 0) {
#pragma unroll
                for (int s2 = 0; s2 < 8; s2++) {
                    const float* pb = &pbuf[(size_t)(s2 * 128) * 4 + b_cell];
                    g0 += pb[(0 * 32 + u_cell) * 4];
                    g1 += pb[(1 * 32 + u_cell) * 4];
                    g2 += pb[(2 * 32 + u_cell) * 4];
                    g3 += pb[(3 * 32 + u_cell) * 4];
                }
            }
            float i_ = 1.f / (1.f + __expf(-g0));
            float f_ = 1.f / (1.f + __expf(-g1));
            float o_ = 1.f / (1.f + __expf(-g3));
            c_state = f_ * c_state + i_ * tanhf(g2);
            float hv = o_ * tanhf(c_state);

            stg[u_cell * 4 + b_cell] = hv;
            out[((size_t)ob * TT + t) * HH + j_cell] = hv;
        }
        __syncthreads();   // staging complete (finished batches keep frozen h)

        // ---- push: one float4 per thread; 8 ranks x 32 rows of 16B (contiguous) ----
        {
            uint32_t prank = (uint32_t)(tid >> 5);
            int pu = tid & 31;
            float4 v = stg4[pu];
            st_cluster_v4(hsw_a + (uint32_t)((rank * 32 + pu) * 16), prank, v);
        }

        xg0 = ng0; xg1 = ng1; xg2 = ng2; xg3 = ng3;
        act = act_n;

        // ---- one hardware cluster barrier per step ----
        CLUSTER_SYNC_();
    }
}

// ---------------- kernel 3: logits = log_softmax(concat(out_f, rev(out_b)) @ W_fc^T) ---
__global__ __launch_bounds__(256)
void logits_kernel(const int* __restrict__ seq_len,
                   const float* __restrict__ W_fc)
{
    int bt = blockIdx.x;
    int b = bt / TT, t = bt % TT;
    int L = seq_len[b];
    if (t >= L) return;

    __shared__ float outs[2 * HH];
    __shared__ float dots[CC];
    __shared__ float lse_s;

    int tid = threadIdx.x;  // 256
    outs[tid]       = g_out_f[(size_t)bt * HH + tid];
    outs[HH + tid]  = g_out_b[(size_t)(b * TT + (L - 1 - t)) * HH + tid];
    __syncthreads();

    int warp = tid >> 5, lane = tid & 31;
    for (int cls = warp; cls < CC; cls += 8) {
        float acc = 0.f;
#pragma unroll 4
        for (int e = lane; e < 2 * HH; e += 32)
            acc += outs[e] * W_fc[cls * (2 * HH) + e];
#pragma unroll
        for (int off = 16; off; off >>= 1)
            acc += __shfl_down_sync(0xffffffffu, acc, off);
        if (lane == 0) dots[cls] = acc;
    }
    __syncthreads();

    if (tid == 0) {
        float m = -INFINITY;
        for (int cI = 0; cI < CC; cI++) m = fmaxf(m, dots[cI]);
        float sum = 0.f;
        for (int cI = 0; cI < CC; cI++) sum += expf(dots[cI] - m);
        lse_s = m + logf(sum);
    }
    __syncthreads();

    if (tid < CC) g_logits[(size_t)bt * CC + tid] = dots[tid] - lse_s;
}

// ---------------- kernel 4: CRF gold score + forward algorithm, warp per batch ----------
__global__ __launch_bounds__(32)
void crf_kernel(const int* __restrict__ seq_len, const int* __restrict__ y,
                const float* __restrict__ start_t, const float* __restrict__ end_t,
                const float* __restrict__ trans)
{
    int b = blockIdx.x;
    int lane = threadIdx.x;  // 32

    __shared__ float trans_s[CC * CC];
    __shared__ float alpha_s[CC];
    for (int i = lane; i < CC * CC; i += 32) trans_s[i] = trans[i];
    __syncwarp();

    int L = seq_len[b];
    const float* lg = g_logits + (size_t)b * TT * CC;
    const int* yb = y + b * TT;

    float part = 0.f;
    for (int t = 1 + lane; t < L; t += 32)
        part += trans_s[yb[t - 1] * CC + yb[t]] + lg[t * CC + yb[t]];
#pragma unroll
    for (int off = 16; off; off >>= 1)
        part += __shfl_down_sync(0xffffffffu, part, off);

    float score = 0.f;
    if (lane == 0)
        score = part + start_t[yb[0]] + lg[yb[0]] + end_t[yb[L - 1]];

    int j = lane;
    float alpha = (j < CC) ? (start_t[j] + lg[j]) : -INFINITY;
    for (int t = 1; t < L; t++) {
        if (j < CC) alpha_s[j] = alpha;
        __syncwarp();
        float na = alpha;
        if (j < CC) {
            float m = -INFINITY;
#pragma unroll
            for (int i = 0; i < CC; i++)
                m = fmaxf(m, alpha_s[i] + trans_s[i * CC + j]);
            float sum = 0.f;
#pragma unroll
            for (int i = 0; i < CC; i++)
                sum += expf(alpha_s[i] + trans_s[i * CC + j] - m);
            na = m + logf(sum) + lg[t * CC + j];
        }
        __syncwarp();
        alpha = na;
    }

    if (j < CC) alpha_s[j] = alpha + end_t[j];
    __syncwarp();
    if (lane == 0) {
        float m = -INFINITY;
        for (int i = 0; i < CC; i++) m = fmaxf(m, alpha_s[i]);
        float sum = 0.f;
        for (int i = 0; i < CC; i++) sum += expf(alpha_s[i] - m);
        float logZ = m + logf(sum);
        g_llh[b] = score - logZ;
    }
}

// ---------------- kernel 5: loss = -sum_b llh[b] ----------------
__global__ __launch_bounds__(32)
void finalize_kernel(float* __restrict__ out)
{
    int lane = threadIdx.x;
    float v = g_llh[lane];
#pragma unroll
    for (int off = 16; off; off >>= 1)
        v += __shfl_down_sync(0xffffffffu, v, off);
    if (lane == 0) out[0] = -v;
}

// ---------------- launch ----------------
extern "C" void kernel_launch(void* const* d_in, const int* in_sizes, int n_in,
                              void* d_out, int out_size)
{
    (void)in_sizes; (void)n_in; (void)out_size;
    const int*   x       = (const int*)  d_in[0];
    const int*   seq_len = (const int*)  d_in[1];
    const int*   y       = (const int*)  d_in[2];
    // d_in[3] = mask (derived from seq_len instead)
    const float* emb     = (const float*)d_in[4];
    const float* Wih_f   = (const float*)d_in[5];
    const float* Whh_f   = (const float*)d_in[6];
    const float* b_f     = (const float*)d_in[7];
    const float* Wih_b   = (const float*)d_in[8];
    const float* Whh_b   = (const float*)d_in[9];
    const float* b_b     = (const float*)d_in[10];
    const float* W_fc    = (const float*)d_in[11];
    const float* start_t = (const float*)d_in[12];
    const float* end_t   = (const float*)d_in[13];
    const float* trans   = (const float*)d_in[14];
    float* out = (float*)d_out;

    // scan dynamic SMEM: Ws 128KB + hs 2x4KB + pbuf 16KB = 152KB
    const int scan_smem = (256 * 128 + 2 * 256 * 4 + 8 * 128 * 4) * (int)sizeof(float);
    static int smem_set = 0;
    if (!smem_set) {
        cudaFuncSetAttribute(lstm_scan4,
                             cudaFuncAttributeMaxDynamicSharedMemorySize, scan_smem);
        smem_set = 1;
    }

    setup_kernel<<<1, 256>>>(seq_len);

    dim3 ggrid(GG / 128, MM / 128);
    gemm_xp<<<ggrid, 256>>>(x, seq_len, emb, Wih_f, b_f, 0);
    gemm_xp<<<ggrid, 256>>>(x, seq_len, emb, Wih_b, b_b, 1);

    lstm_scan4<<<128, 256, scan_smem>>>(Whh_f, Whh_b);

    logits_kernel<<<MM, 256>>>(seq_len, W_fc);

    crf_kernel<<<BB, 32>>>(seq_len, y, start_t, end_t, trans);

    finalize_kernel<<<1, 32>>>(out);
}

// round 15
// speedup vs baseline: 1.4067x; 1.0037x over previous
#include <cuda_runtime.h>
#include <math.h>
#include <stdint.h>

// Problem constants
#define BB 32
#define TT 512
#define EE 256
#define HH 256
#define GG 1024          // 4*H
#define CC 20
#define MM (BB * TT)     // 16384

typedef unsigned long long ull;

// ---------------- f32x2 packed helpers (Blackwell) ----------------
__device__ __forceinline__ ull dup_f32(float x) {
    ull r;
    asm("mov.b64 %0, {%1, %1};" : "=l"(r) : "f"(x));
    return r;
}
__device__ __forceinline__ ull pack_f32(float lo, float hi) {
    ull r;
    asm("mov.b64 %0, {%1, %2};" : "=l"(r) : "f"(lo), "f"(hi));
    return r;
}
__device__ __forceinline__ void ffma2(ull& acc, ull a, ull b) {
    asm("fma.rn.f32x2 %0, %1, %2, %0;" : "+l"(acc) : "l"(a), "l"(b));
}
__device__ __forceinline__ float2 unpack_f32(ull v) {
    float lo, hi;
    asm("mov.b64 {%0, %1}, %2;" : "=f"(lo), "=f"(hi) : "l"(v));
    return make_float2(lo, hi);
}

// ---------------- cluster / DSMEM helpers ----------------
__device__ __forceinline__ uint32_t smem_u32(const void* p) {
    uint32_t a;
    asm("{ .reg .u64 t; cvta.to.shared.u64 t, %1; cvt.u32.u64 %0, t; }"
        : "=r"(a) : "l"(p));
    return a;
}
__device__ __forceinline__ void st_cluster_v4(uint32_t local_addr, uint32_t rank, float4 v) {
    uint32_t ra;
    asm("mapa.shared::cluster.u32 %0, %1, %2;" : "=r"(ra) : "r"(local_addr), "r"(rank));
    asm volatile("st.shared::cluster.v4.f32 [%0], {%1, %2, %3, %4};"
                 :: "r"(ra), "f"(v.x), "f"(v.y), "f"(v.z), "f"(v.w) : "memory");
}
#define CLUSTER_SYNC_() do { \
    asm volatile("barrier.cluster.arrive.aligned;" ::: "memory"); \
    asm volatile("barrier.cluster.wait.aligned;" ::: "memory"); } while (0)

// ---------------- device scratch (allocation-free rule: static __device__) --------------
__device__ float g_xp_f[(size_t)MM * GG];   // 64 MB
__device__ float g_xp_b[(size_t)MM * GG];   // 64 MB
__device__ float g_out_f[(size_t)MM * HH];  // 16 MB
__device__ float g_out_b[(size_t)MM * HH];  // 16 MB
__device__ float g_logits[(size_t)MM * CC];
__device__ float g_llh[BB];

// scan bookkeeping
__device__ int g_perm[BB];                  // sorted(batch) -> original batch
__device__ int g_Lsorted[BB];               // lengths, descending

// GEMM compaction
__device__ int g_rows[MM];                  // packed (b<<16)|t for t < seq_len[b]
__device__ int g_nrows;

// ---------------- kernel 0: setup ----------------
__global__ __launch_bounds__(256)
void setup_kernel(const int* __restrict__ seq_len)
{
    __shared__ int off_s[BB + 1];
    int tid = threadIdx.x;

    if (tid == 0) {
        int L[BB], p[BB];
        for (int i = 0; i < BB; i++) { L[i] = seq_len[i]; p[i] = i; }
        // stable insertion sort, descending by L
        for (int i = 1; i < BB; i++) {
            int kl = L[i], kp = p[i];
            int j = i - 1;
            while (j >= 0 && L[j] < kl) { L[j + 1] = L[j]; p[j + 1] = p[j]; j--; }
            L[j + 1] = kl; p[j + 1] = kp;
        }
        for (int i = 0; i < BB; i++) { g_perm[i] = p[i]; g_Lsorted[i] = L[i]; }
        // prefix offsets in ORIGINAL batch order for row compaction
        int off = 0;
        for (int b = 0; b < BB; b++) { off_s[b] = off; off += seq_len[b]; }
        off_s[BB] = off;
        g_nrows = off;
    }
    __syncthreads();

    // fill compacted row list: thread group (b, r) writes rows t = r, r+8, ...
    int b = tid >> 3, r = tid & 7;
    int off = off_s[b];
    int L = off_s[b + 1] - off;
    for (int t = r; t < L; t += 8)
        g_rows[off + t] = (b << 16) | t;
}

// ---------------- kernel 1: xp = gather(emb, x[, reversed]) @ Wih^T + bias -------------
// Compacted M (only t < seq_len rows). Tile 128x128, BK=8, 256 threads, 8x8 per thread.
// Double-buffered SMEM (one __syncthreads per k-tile, LDG hidden under compute),
// pack-free f32x2 inner loop (Bs read as ulonglong2).
__global__ __launch_bounds__(256)
void gemm_xp(const int* __restrict__ x, const int* __restrict__ seq_len,
             const float* __restrict__ emb, const float* __restrict__ Wih,
             const float* __restrict__ bias, int rev)
{
    const int BM = 128, BN = 128, BK = 8, NT = EE / BK;   // 32 k-tiles
    __shared__ float As[2][BK][BM];
    __shared__ float Bs[2][BK][BN];
    __shared__ int tok[BM];
    __shared__ int orow[BM];

    int nrows = g_nrows;
    int m0 = blockIdx.y * BM;
    if (m0 >= nrows) return;

    float* __restrict__ xp = rev ? g_xp_b : g_xp_f;

    int tid = threadIdx.x;                 // 256
    int n0 = blockIdx.x * BN;

    if (tid < BM) {
        int m = m0 + tid;
        if (m < nrows) {
            int pk = g_rows[m];
            int b = pk >> 16, t = pk & 0xFFFF;
            int tp = rev ? (seq_len[b] - 1 - t) : t;   // t < L by construction
            tok[tid]  = x[b * TT + tp];
            orow[tid] = b * TT + t;
        } else {
            tok[tid] = 0;
            orow[tid] = -1;
        }
    }
    __syncthreads();

    int tx = tid & 15, ty = tid >> 4;
    int am = tid >> 1, ak = (tid & 1) * 4;
    int bn = tid >> 1, bk = (tid & 1) * 4;

    const float* a_src = &emb[(size_t)tok[am] * EE + ak];
    const float* b_src = &Wih[(size_t)(n0 + bn) * EE + bk];

    ull acc2[8][4];
#pragma unroll
    for (int i = 0; i < 8; i++)
#pragma unroll
        for (int j = 0; j < 4; j++) acc2[i][j] = 0ull;

    // ---- prologue: tile 0 ----
    float4 av = *reinterpret_cast<const float4*>(a_src);
    float4 bv = *reinterpret_cast<const float4*>(b_src);
    As[0][ak + 0][am] = av.x; As[0][ak + 1][am] = av.y;
    As[0][ak + 2][am] = av.z; As[0][ak + 3][am] = av.w;
    Bs[0][bk + 0][bn] = bv.x; Bs[0][bk + 1][bn] = bv.y;
    Bs[0][bk + 2][bn] = bv.z; Bs[0][bk + 3][bn] = bv.w;
    __syncthreads();

    for (int k0 = 0; k0 < NT; k0++) {
        int buf = k0 & 1;

        // issue LDG for tile k0+1 (latency hidden under this tile's compute)
        if (k0 + 1 < NT) {
            av = *reinterpret_cast<const float4*>(a_src + (k0 + 1) * BK);
            bv = *reinterpret_cast<const float4*>(b_src + (k0 + 1) * BK);
        }

#pragma unroll
        for (int kk = 0; kk < BK; kk++) {
            float a[8];
            *reinterpret_cast<float4*>(&a[0]) =
                *reinterpret_cast<const float4*>(&As[buf][kk][ty * 8]);
            *reinterpret_cast<float4*>(&a[4]) =
                *reinterpret_cast<const float4*>(&As[buf][kk][ty * 8 + 4]);
            // Bs pairs read directly as packed f32x2 (no mov.b64 packs)
            ulonglong2 bp01 = *reinterpret_cast<const ulonglong2*>(&Bs[buf][kk][tx * 8]);
            ulonglong2 bp23 = *reinterpret_cast<const ulonglong2*>(&Bs[buf][kk][tx * 8 + 4]);
            ull bp[4] = { bp01.x, bp01.y, bp23.x, bp23.y };
#pragma unroll
            for (int i = 0; i < 8; i++) {
                ull ai = dup_f32(a[i]);
#pragma unroll
                for (int j = 0; j < 4; j++) ffma2(acc2[i][j], ai, bp[j]);
            }
        }

        if (k0 + 1 < NT) {
            int nb = buf ^ 1;
            As[nb][ak + 0][am] = av.x; As[nb][ak + 1][am] = av.y;
            As[nb][ak + 2][am] = av.z; As[nb][ak + 3][am] = av.w;
            Bs[nb][bk + 0][bn] = bv.x; Bs[nb][bk + 1][bn] = bv.y;
            Bs[nb][bk + 2][bn] = bv.z; Bs[nb][bk + 3][bn] = bv.w;
            __syncthreads();
        }
    }

    float bj[8];
#pragma unroll
    for (int j = 0; j < 8; j++) bj[j] = bias[n0 + tx * 8 + j];
#pragma unroll
    for (int i = 0; i < 8; i++) {
        int om = orow[ty * 8 + i];
        if (om >= 0) {
            size_t row = (size_t)om * GG + n0 + tx * 8;
            float2 p0 = unpack_f32(acc2[i][0]);
            float2 p1 = unpack_f32(acc2[i][1]);
            float2 p2 = unpack_f32(acc2[i][2]);
            float2 p3 = unpack_f32(acc2[i][3]);
            float4 v0, v1;
            v0.x = p0.x + bj[0]; v0.y = p0.y + bj[1];
            v0.z = p1.x + bj[2]; v0.w = p1.y + bj[3];
            v1.x = p2.x + bj[4]; v1.y = p2.y + bj[5];
            v1.z = p3.x + bj[6]; v1.w = p3.y + bj[7];
            *reinterpret_cast<float4*>(&xp[row]) = v0;
            *reinterpret_cast<float4*>(&xp[row + 4]) = v1;
        }
    }
}

// ---------------- kernel 2: clustered LSTM scan (R14, frozen) ---------------------------
// 128 CTAs = 16 clusters x 8. cluster cid: dir = cid&1, grp = cid>>1 (4 sorted batches).
// CTA rank owns hidden units [rank*32, rank*32+32) -> 128 gate rows of Whh (128KB) in
// SMEM for the whole scan. Per step: 128row x 4batch x 256k micro-GEMM from SMEM,
// cell update into a staging buffer, ONE float4 remote store per thread (8 ranks x 32
// rows of 16B), ONE hardware cluster barrier. xp loads are software double-buffered
// one step ahead so DRAM latency never sits on the barrier-to-barrier critical path.
__global__ __launch_bounds__(256) __cluster_dims__(8, 1, 1)
void lstm_scan4(const float* __restrict__ Whh_f, const float* __restrict__ Whh_b)
{
    extern __shared__ float sm[];
    float* Ws   = sm;                       // [256][128]  Ws[k*128 + lrow], lrow = q*32+u
    float* hs0  = sm + 256 * 128;           // [256][4]    h buffer parity 0
    float* hs1  = hs0 + 256 * 4;            // [256][4]    h buffer parity 1
    float* pbuf = hs1 + 256 * 4;            // [8][128][4] pbuf[(s*128+row)*4 + b]

    __shared__ float4 stg4[32];             // staged h: stg4[u] = (b0,b1,b2,b3)
    __shared__ int perm_s[4];
    __shared__ int Ls_s[4];

    int bid  = blockIdx.x;
    int cid  = bid >> 3;
    int rank = bid & 7;
    int dir  = cid & 1;
    int grp  = cid >> 1;
    int tid  = threadIdx.x;

    const float* __restrict__ xp  = dir ? g_xp_b : g_xp_f;
    const float* __restrict__ Whh = dir ? Whh_b : Whh_f;
    float* __restrict__ out       = dir ? g_out_b : g_out_f;

    if (tid < 4) {
        perm_s[tid] = g_perm[grp * 4 + tid];
        Ls_s[tid]   = g_Lsorted[grp * 4 + tid];
    }
    int Lmax = g_Lsorted[grp * 4];          // group sorted desc -> first is longest

    // ---- load this CTA's 128 gate rows of Whh into SMEM, k-major ----
    for (int i = tid; i < 128 * 64; i += 256) {
        int lrow = i & 127, k4 = i >> 7;
        int q = lrow >> 5, u = lrow & 31;
        int grow = q * 256 + rank * 32 + u;
        float4 w = *reinterpret_cast<const float4*>(&Whh[(size_t)grow * 256 + k4 * 4]);
        Ws[(k4 * 4 + 0) * 128 + lrow] = w.x;
        Ws[(k4 * 4 + 1) * 128 + lrow] = w.y;
        Ws[(k4 * 4 + 2) * 128 + lrow] = w.z;
        Ws[(k4 * 4 + 3) * 128 + lrow] = w.w;
    }
    __syncthreads();
    CLUSTER_SYNC_();   // all SMEM ready before any DSMEM pushes

    // GEMM roles: s = k-slice (8 x 32k), rowg = 4-row group (32)
    int s    = tid >> 5;
    int rowg = tid & 31;
    // cell roles (tid < 128): b_cell 0..3, u_cell 0..31
    int b_cell = tid >> 5;
    int u_cell = tid & 31;
    int j_cell = rank * 32 + u_cell;

    uint32_t hs0_a = smem_u32(hs0);
    uint32_t hs1_a = smem_u32(hs1);

    const float4* W4 = reinterpret_cast<const float4*>(Ws);
    float4* P4 = reinterpret_cast<float4*>(pbuf);
    float* stg = reinterpret_cast<float*>(stg4);

    float c_state = 0.f;
    bool cellth = tid < 128;
    int ob = cellth ? perm_s[b_cell] : 0;

    // ---- prologue: prefetch xp gate values for t = 0 (all batches have L >= 1) ----
    bool act = cellth;
    float xg0 = 0.f, xg1 = 0.f, xg2 = 0.f, xg3 = 0.f;
    if (cellth) {
        size_t xb = (size_t)ob * TT * GG + (size_t)rank * 32 + u_cell;
        xg0 = xp[xb];
        xg1 = xp[xb + 256];
        xg2 = xp[xb + 512];
        xg3 = xp[xb + 768];
    }

    for (int t = 0; t < Lmax; t++) {
        int pr = t & 1;
        const float4* H4 = reinterpret_cast<const float4*>(pr ? hs1 : hs0);
        uint32_t hsw_a = pr ? hs0_a : hs1_a;   // write opposite parity

        // ---- issue prefetch for step t+1 (hidden under GEMM + barrier) ----
        bool act_n = cellth && (t + 1 < Ls_s[b_cell]);
        float ng0 = 0.f, ng1 = 0.f, ng2 = 0.f, ng3 = 0.f;
        if (act_n) {
            size_t xb = ((size_t)ob * TT + (t + 1)) * GG + (size_t)rank * 32 + u_cell;
            ng0 = xp[xb];
            ng1 = xp[xb + 256];
            ng2 = xp[xb + 512];
            ng3 = xp[xb + 768];
        }

        // ---- micro-GEMM over k-slice s (32 k), rows rowg*4..+4, all 4 batches ----
        if (t > 0) {
            ull acc2[4][2];
#pragma unroll
            for (int i = 0; i < 4; i++) { acc2[i][0] = 0ull; acc2[i][1] = 0ull; }
            int kbase = s * 32;
#pragma unroll 8
            for (int k = 0; k < 32; k++) {
                float4 wv = W4[(kbase + k) * 32 + rowg];
                float4 hv = H4[kbase + k];
                ull h01 = pack_f32(hv.x, hv.y);
                ull h23 = pack_f32(hv.z, hv.w);
                ull w;
                w = dup_f32(wv.x); ffma2(acc2[0][0], w, h01); ffma2(acc2[0][1], w, h23);
                w = dup_f32(wv.y); ffma2(acc2[1][0], w, h01); ffma2(acc2[1][1], w, h23);
                w = dup_f32(wv.z); ffma2(acc2[2][0], w, h01); ffma2(acc2[2][1], w, h23);
                w = dup_f32(wv.w); ffma2(acc2[3][0], w, h01); ffma2(acc2[3][1], w, h23);
            }
#pragma unroll
            for (int i = 0; i < 4; i++) {
                float2 p0 = unpack_f32(acc2[i][0]);
                float2 p1 = unpack_f32(acc2[i][1]);
                float4 v; v.x = p0.x; v.y = p0.y; v.z = p1.x; v.w = p1.y;
                P4[s * 128 + rowg * 4 + i] = v;
            }
        }
        __syncthreads();

        // ---- reduce 8 k-slices + cell update -> staging buffer + out ----
        if (act) {
            float g0 = xg0, g1 = xg1, g2 = xg2, g3 = xg3;
            if (t > 0) {
#pragma unroll
                for (int s2 = 0; s2 < 8; s2++) {
                    const float* pb = &pbuf[(size_t)(s2 * 128) * 4 + b_cell];
                    g0 += pb[(0 * 32 + u_cell) * 4];
                    g1 += pb[(1 * 32 + u_cell) * 4];
                    g2 += pb[(2 * 32 + u_cell) * 4];
                    g3 += pb[(3 * 32 + u_cell) * 4];
                }
            }
            float i_ = 1.f / (1.f + __expf(-g0));
            float f_ = 1.f / (1.f + __expf(-g1));
            float o_ = 1.f / (1.f + __expf(-g3));
            c_state = f_ * c_state + i_ * tanhf(g2);
            float hv = o_ * tanhf(c_state);

            stg[u_cell * 4 + b_cell] = hv;
            out[((size_t)ob * TT + t) * HH + j_cell] = hv;
        }
        __syncthreads();   // staging complete (finished batches keep frozen h)

        // ---- push: one float4 per thread; 8 ranks x 32 rows of 16B (contiguous) ----
        {
            uint32_t prank = (uint32_t)(tid >> 5);
            int pu = tid & 31;
            float4 v = stg4[pu];
            st_cluster_v4(hsw_a + (uint32_t)((rank * 32 + pu) * 16), prank, v);
        }

        xg0 = ng0; xg1 = ng1; xg2 = ng2; xg3 = ng3;
        act = act_n;

        // ---- one hardware cluster barrier per step ----
        CLUSTER_SYNC_();
    }
}

// ---------------- kernel 3: logits = log_softmax(concat(out_f, rev(out_b)) @ W_fc^T) ---
__global__ __launch_bounds__(256)
void logits_kernel(const int* __restrict__ seq_len,
                   const float* __restrict__ W_fc)
{
    int bt = blockIdx.x;
    int b = bt / TT, t = bt % TT;
    int L = seq_len[b];
    if (t >= L) return;

    __shared__ float outs[2 * HH];
    __shared__ float dots[CC];
    __shared__ float lse_s;

    int tid = threadIdx.x;  // 256
    outs[tid]       = g_out_f[(size_t)bt * HH + tid];
    outs[HH + tid]  = g_out_b[(size_t)(b * TT + (L - 1 - t)) * HH + tid];
    __syncthreads();

    int warp = tid >> 5, lane = tid & 31;
    for (int cls = warp; cls < CC; cls += 8) {
        float acc = 0.f;
#pragma unroll 4
        for (int e = lane; e < 2 * HH; e += 32)
            acc += outs[e] * W_fc[cls * (2 * HH) + e];
#pragma unroll
        for (int off = 16; off; off >>= 1)
            acc += __shfl_down_sync(0xffffffffu, acc, off);
        if (lane == 0) dots[cls] = acc;
    }
    __syncthreads();

    if (tid == 0) {
        float m = -INFINITY;
        for (int cI = 0; cI < CC; cI++) m = fmaxf(m, dots[cI]);
        float sum = 0.f;
        for (int cI = 0; cI < CC; cI++) sum += expf(dots[cI] - m);
        lse_s = m + logf(sum);
    }
    __syncthreads();

    if (tid < CC) g_logits[(size_t)bt * CC + tid] = dots[tid] - lse_s;
}

// ---------------- kernel 4: CRF gold score + forward algorithm, warp per batch ----------
__global__ __launch_bounds__(32)
void crf_kernel(const int* __restrict__ seq_len, const int* __restrict__ y,
                const float* __restrict__ start_t, const float* __restrict__ end_t,
                const float* __restrict__ trans)
{
    int b = blockIdx.x;
    int lane = threadIdx.x;  // 32

    __shared__ float trans_s[CC * CC];
    __shared__ float alpha_s[CC];
    for (int i = lane; i < CC * CC; i += 32) trans_s[i] = trans[i];
    __syncwarp();

    int L = seq_len[b];
    const float* lg = g_logits + (size_t)b * TT * CC;
    const int* yb = y + b * TT;

    float part = 0.f;
    for (int t = 1 + lane; t < L; t += 32)
        part += trans_s[yb[t - 1] * CC + yb[t]] + lg[t * CC + yb[t]];
#pragma unroll
    for (int off = 16; off; off >>= 1)
        part += __shfl_down_sync(0xffffffffu, part, off);

    float score = 0.f;
    if (lane == 0)
        score = part + start_t[yb[0]] + lg[yb[0]] + end_t[yb[L - 1]];

    int j = lane;
    float alpha = (j < CC) ? (start_t[j] + lg[j]) : -INFINITY;
    for (int t = 1; t < L; t++) {
        if (j < CC) alpha_s[j] = alpha;
        __syncwarp();
        float na = alpha;
        if (j < CC) {
            float m = -INFINITY;
#pragma unroll
            for (int i = 0; i < CC; i++)
                m = fmaxf(m, alpha_s[i] + trans_s[i * CC + j]);
            float sum = 0.f;
#pragma unroll
            for (int i = 0; i < CC; i++)
                sum += expf(alpha_s[i] + trans_s[i * CC + j] - m);
            na = m + logf(sum) + lg[t * CC + j];
        }
        __syncwarp();
        alpha = na;
    }

    if (j < CC) alpha_s[j] = alpha + end_t[j];
    __syncwarp();
    if (lane == 0) {
        float m = -INFINITY;
        for (int i = 0; i < CC; i++) m = fmaxf(m, alpha_s[i]);
        float sum = 0.f;
        for (int i = 0; i < CC; i++) sum += expf(alpha_s[i] - m);
        float logZ = m + logf(sum);
        g_llh[b] = score - logZ;
    }
}

// ---------------- kernel 5: loss = -sum_b llh[b] ----------------
__global__ __launch_bounds__(32)
void finalize_kernel(float* __restrict__ out)
{
    int lane = threadIdx.x;
    float v = g_llh[lane];
#pragma unroll
    for (int off = 16; off; off >>= 1)
        v += __shfl_down_sync(0xffffffffu, v, off);
    if (lane == 0) out[0] = -v;
}

// ---------------- launch ----------------
extern "C" void kernel_launch(void* const* d_in, const int* in_sizes, int n_in,
                              void* d_out, int out_size)
{
    (void)in_sizes; (void)n_in; (void)out_size;
    const int*   x       = (const int*)  d_in[0];
    const int*   seq_len = (const int*)  d_in[1];
    const int*   y       = (const int*)  d_in[2];
    // d_in[3] = mask (derived from seq_len instead)
    const float* emb     = (const float*)d_in[4];
    const float* Wih_f   = (const float*)d_in[5];
    const float* Whh_f   = (const float*)d_in[6];
    const float* b_f     = (const float*)d_in[7];
    const float* Wih_b   = (const float*)d_in[8];
    const float* Whh_b   = (const float*)d_in[9];
    const float* b_b     = (const float*)d_in[10];
    const float* W_fc    = (const float*)d_in[11];
    const float* start_t = (const float*)d_in[12];
    const float* end_t   = (const float*)d_in[13];
    const float* trans   = (const float*)d_in[14];
    float* out = (float*)d_out;

    // scan dynamic SMEM: Ws 128KB + hs 2x4KB + pbuf 16KB = 152KB
    const int scan_smem = (256 * 128 + 2 * 256 * 4 + 8 * 128 * 4) * (int)sizeof(float);
    static int smem_set = 0;
    if (!smem_set) {
        cudaFuncSetAttribute(lstm_scan4,
                             cudaFuncAttributeMaxDynamicSharedMemorySize, scan_smem);
        smem_set = 1;
    }

    setup_kernel<<<1, 256>>>(seq_len);

    dim3 ggrid(GG / 128, MM / 128);
    gemm_xp<<<ggrid, 256>>>(x, seq_len, emb, Wih_f, b_f, 0);
    gemm_xp<<<ggrid, 256>>>(x, seq_len, emb, Wih_b, b_b, 1);

    lstm_scan4<<<128, 256, scan_smem>>>(Whh_f, Whh_b);

    logits_kernel<<<MM, 256>>>(seq_len, W_fc);

    crf_kernel<<<BB, 32>>>(seq_len, y, start_t, end_t, trans);

    finalize_kernel<<<1, 32>>>(out);
}

// round 16
// speedup vs baseline: 1.5180x; 1.0792x over previous
#include <cuda_runtime.h>
#include <math.h>
#include <stdint.h>

// Problem constants
#define BB 32
#define TT 512
#define EE 256
#define HH 256
#define GG 1024          // 4*H
#define CC 20
#define MM (BB * TT)     // 16384

typedef unsigned long long ull;

// ---------------- f32x2 packed helpers (Blackwell) ----------------
__device__ __forceinline__ ull dup_f32(float x) {
    ull r;
    asm("mov.b64 %0, {%1, %1};" : "=l"(r) : "f"(x));
    return r;
}
__device__ __forceinline__ void ffma2(ull& acc, ull a, ull b) {
    asm("fma.rn.f32x2 %0, %1, %2, %0;" : "+l"(acc) : "l"(a), "l"(b));
}
__device__ __forceinline__ float2 unpack_f32(ull v) {
    float lo, hi;
    asm("mov.b64 {%0, %1}, %2;" : "=f"(lo), "=f"(hi) : "l"(v));
    return make_float2(lo, hi);
}

// ---------------- tf32 mma helpers ----------------
__device__ __forceinline__ uint32_t to_tf32(float v) {
    uint32_t r;
    asm("cvt.rna.tf32.f32 %0, %1;" : "=r"(r) : "f"(v));
    return r;
}
__device__ __forceinline__ void mma_tf32(float* d, const uint32_t* a,
                                         uint32_t b0, uint32_t b1) {
    asm volatile(
        "mma.sync.aligned.m16n8k8.row.col.f32.tf32.tf32.f32 "
        "{%0,%1,%2,%3}, {%4,%5,%6,%7}, {%8,%9}, {%0,%1,%2,%3};"
        : "+f"(d[0]), "+f"(d[1]), "+f"(d[2]), "+f"(d[3])
        : "r"(a[0]), "r"(a[1]), "r"(a[2]), "r"(a[3]), "r"(b0), "r"(b1));
}

// ---------------- cluster / DSMEM helpers ----------------
__device__ __forceinline__ uint32_t smem_u32(const void* p) {
    uint32_t a;
    asm("{ .reg .u64 t; cvta.to.shared.u64 t, %1; cvt.u32.u64 %0, t; }"
        : "=r"(a) : "l"(p));
    return a;
}
__device__ __forceinline__ void st_cluster_v4(uint32_t local_addr, uint32_t rank, float4 v) {
    uint32_t ra;
    asm("mapa.shared::cluster.u32 %0, %1, %2;" : "=r"(ra) : "r"(local_addr), "r"(rank));
    asm volatile("st.shared::cluster.v4.f32 [%0], {%1, %2, %3, %4};"
                 :: "r"(ra), "f"(v.x), "f"(v.y), "f"(v.z), "f"(v.w) : "memory");
}
#define CLUSTER_SYNC_() do { \
    asm volatile("barrier.cluster.arrive.aligned;" ::: "memory"); \
    asm volatile("barrier.cluster.wait.aligned;" ::: "memory"); } while (0)

// ---------------- device scratch (allocation-free rule: static __device__) --------------
__device__ float g_xp_f[(size_t)MM * GG];   // 64 MB
__device__ float g_xp_b[(size_t)MM * GG];   // 64 MB
__device__ float g_out_f[(size_t)MM * HH];  // 16 MB
__device__ float g_out_b[(size_t)MM * HH];  // 16 MB
__device__ float g_logits[(size_t)MM * CC];
__device__ float g_llh[BB];

// scan bookkeeping
__device__ int g_perm[BB];                  // sorted(batch) -> original batch
__device__ int g_Lsorted[BB];               // lengths, descending

// GEMM compaction
__device__ int g_rows[MM];                  // packed (b<<16)|t for t < seq_len[b]
__device__ int g_nrows;

// ---------------- kernel 0: setup ----------------
__global__ __launch_bounds__(256)
void setup_kernel(const int* __restrict__ seq_len)
{
    __shared__ int off_s[BB + 1];
    int tid = threadIdx.x;

    if (tid == 0) {
        int L[BB], p[BB];
        for (int i = 0; i < BB; i++) { L[i] = seq_len[i]; p[i] = i; }
        // stable insertion sort, descending by L
        for (int i = 1; i < BB; i++) {
            int kl = L[i], kp = p[i];
            int j = i - 1;
            while (j >= 0 && L[j] < kl) { L[j + 1] = L[j]; p[j + 1] = p[j]; j--; }
            L[j + 1] = kl; p[j + 1] = kp;
        }
        for (int i = 0; i < BB; i++) { g_perm[i] = p[i]; g_Lsorted[i] = L[i]; }
        // prefix offsets in ORIGINAL batch order for row compaction
        int off = 0;
        for (int b = 0; b < BB; b++) { off_s[b] = off; off += seq_len[b]; }
        off_s[BB] = off;
        g_nrows = off;
    }
    __syncthreads();

    // fill compacted row list: thread group (b, r) writes rows t = r, r+8, ...
    int b = tid >> 3, r = tid & 7;
    int off = off_s[b];
    int L = off_s[b + 1] - off;
    for (int t = r; t < L; t += 8)
        g_rows[off + t] = (b << 16) | t;
}

// ---------------- kernel 1: xp = gather(emb, x[, reversed]) @ Wih^T + bias -------------
// Compacted M. Tile 128x128, BK=16, 256 threads, tf32 mma.sync (m16n8k8).
// Warps 4(m) x 2(n): each warp 32x64 via 2x8 fragment tiles, fp32 accumulate.
__global__ __launch_bounds__(256)
void gemm_xp(const int* __restrict__ x, const int* __restrict__ seq_len,
             const float* __restrict__ emb, const float* __restrict__ Wih,
             const float* __restrict__ bias, int rev)
{
    const int BM = 128, BN = 128, BK = 16, NCH = EE / BK;   // 16 chunks
    const int LDA = BK + 4;                                  // stride 20: conflict-free frags
    __shared__ float As[BM][LDA];
    __shared__ float Bs[BN][LDA];
    __shared__ int tok[BM];
    __shared__ int orow[BM];

    int nrows = g_nrows;
    int m0 = blockIdx.y * BM;
    if (m0 >= nrows) return;

    float* __restrict__ xp = rev ? g_xp_b : g_xp_f;

    int tid = threadIdx.x;                 // 256
    int n0 = blockIdx.x * BN;

    if (tid < BM) {
        int m = m0 + tid;
        if (m < nrows) {
            int pk = g_rows[m];
            int b = pk >> 16, t = pk & 0xFFFF;
            int tp = rev ? (seq_len[b] - 1 - t) : t;   // t < L by construction
            tok[tid]  = x[b * TT + tp];
            orow[tid] = b * TT + t;
        } else {
            tok[tid] = 0;
            orow[tid] = -1;
        }
    }
    __syncthreads();

    // staging roles: thread -> row ar, k-half ac (8 floats = 2 float4)
    int ar = tid >> 1, ac = (tid & 1) * 8;
    const float* a_src = &emb[(size_t)tok[ar] * EE + ac];
    const float* b_src = &Wih[(size_t)(n0 + ar) * EE + ac];

    // fragment roles
    int wid  = tid >> 5, lane = tid & 31;
    int warpM = wid & 3;        // 4 m-warps of 32 rows
    int warpN = wid >> 2;       // 2 n-warps of 64 cols
    int gID = lane >> 2, tig = lane & 3;

    float d[2][8][4];
#pragma unroll
    for (int mt = 0; mt < 2; mt++)
#pragma unroll
        for (int nt = 0; nt < 8; nt++)
#pragma unroll
            for (int e = 0; e < 4; e++) d[mt][nt][e] = 0.f;

    for (int ch = 0; ch < NCH; ch++) {
        int k0 = ch * BK;
        float4 av0 = *reinterpret_cast<const float4*>(a_src + k0);
        float4 av1 = *reinterpret_cast<const float4*>(a_src + k0 + 4);
        float4 bv0 = *reinterpret_cast<const float4*>(b_src + k0);
        float4 bv1 = *reinterpret_cast<const float4*>(b_src + k0 + 4);
        __syncthreads();   // previous chunk fully consumed
        As[ar][ac + 0] = av0.x; As[ar][ac + 1] = av0.y;
        As[ar][ac + 2] = av0.z; As[ar][ac + 3] = av0.w;
        As[ar][ac + 4] = av1.x; As[ar][ac + 5] = av1.y;
        As[ar][ac + 6] = av1.z; As[ar][ac + 7] = av1.w;
        Bs[ar][ac + 0] = bv0.x; Bs[ar][ac + 1] = bv0.y;
        Bs[ar][ac + 2] = bv0.z; Bs[ar][ac + 3] = bv0.w;
        Bs[ar][ac + 4] = bv1.x; Bs[ar][ac + 5] = bv1.y;
        Bs[ar][ac + 6] = bv1.z; Bs[ar][ac + 7] = bv1.w;
        __syncthreads();

#pragma unroll
        for (int ks = 0; ks < 2; ks++) {
            int kb = ks * 8;
            // A fragments for the 2 m-tiles
            uint32_t at[2][4];
#pragma unroll
            for (int mt = 0; mt < 2; mt++) {
                int r = warpM * 32 + mt * 16 + gID;
                at[mt][0] = to_tf32(As[r    ][kb + tig    ]);
                at[mt][1] = to_tf32(As[r + 8][kb + tig    ]);
                at[mt][2] = to_tf32(As[r    ][kb + tig + 4]);
                at[mt][3] = to_tf32(As[r + 8][kb + tig + 4]);
            }
            // B fragments + mma per n-tile
#pragma unroll
            for (int nt = 0; nt < 8; nt++) {
                int n = warpN * 64 + nt * 8 + gID;
                uint32_t b0 = to_tf32(Bs[n][kb + tig    ]);
                uint32_t b1 = to_tf32(Bs[n][kb + tig + 4]);
                mma_tf32(d[0][nt], at[0], b0, b1);
                mma_tf32(d[1][nt], at[1], b0, b1);
            }
        }
    }

    // epilogue: bias + scattered float2 stores per fragment
#pragma unroll
    for (int mt = 0; mt < 2; mt++) {
        int r0 = warpM * 32 + mt * 16 + gID;
#pragma unroll
        for (int nt = 0; nt < 8; nt++) {
            int n = n0 + warpN * 64 + nt * 8 + tig * 2;
            float bj0 = bias[n], bj1 = bias[n + 1];
            int om = orow[r0];
            if (om >= 0) {
                float2 v; v.x = d[mt][nt][0] + bj0; v.y = d[mt][nt][1] + bj1;
                *reinterpret_cast<float2*>(&xp[(size_t)om * GG + n]) = v;
            }
            int om2 = orow[r0 + 8];
            if (om2 >= 0) {
                float2 v; v.x = d[mt][nt][2] + bj0; v.y = d[mt][nt][3] + bj1;
                *reinterpret_cast<float2*>(&xp[(size_t)om2 * GG + n]) = v;
            }
        }
    }
}

// ---------------- kernel 2: clustered LSTM scan (R14, frozen; H read as ulonglong2) ----
// 128 CTAs = 16 clusters x 8. cluster cid: dir = cid&1, grp = cid>>1 (4 sorted batches).
// CTA rank owns hidden units [rank*32, rank*32+32) -> 128 gate rows of Whh (128KB) in
// SMEM for the whole scan. Per step: 128row x 4batch x 256k micro-GEMM from SMEM,
// cell update into a staging buffer, ONE float4 remote store per thread, ONE hardware
// cluster barrier. xp loads are software double-buffered one step ahead.
__global__ __launch_bounds__(256) __cluster_dims__(8, 1, 1)
void lstm_scan4(const float* __restrict__ Whh_f, const float* __restrict__ Whh_b)
{
    extern __shared__ float sm[];
    float* Ws   = sm;                       // [256][128]  Ws[k*128 + lrow], lrow = q*32+u
    float* hs0  = sm + 256 * 128;           // [256][4]    h buffer parity 0
    float* hs1  = hs0 + 256 * 4;            // [256][4]    h buffer parity 1
    float* pbuf = hs1 + 256 * 4;            // [8][128][4] pbuf[(s*128+row)*4 + b]

    __shared__ float4 stg4[32];             // staged h: stg4[u] = (b0,b1,b2,b3)
    __shared__ int perm_s[4];
    __shared__ int Ls_s[4];

    int bid  = blockIdx.x;
    int cid  = bid >> 3;
    int rank = bid & 7;
    int dir  = cid & 1;
    int grp  = cid >> 1;
    int tid  = threadIdx.x;

    const float* __restrict__ xp  = dir ? g_xp_b : g_xp_f;
    const float* __restrict__ Whh = dir ? Whh_b : Whh_f;
    float* __restrict__ out       = dir ? g_out_b : g_out_f;

    if (tid < 4) {
        perm_s[tid] = g_perm[grp * 4 + tid];
        Ls_s[tid]   = g_Lsorted[grp * 4 + tid];
    }
    int Lmax = g_Lsorted[grp * 4];          // group sorted desc -> first is longest

    // ---- load this CTA's 128 gate rows of Whh into SMEM, k-major ----
    for (int i = tid; i < 128 * 64; i += 256) {
        int lrow = i & 127, k4 = i >> 7;
        int q = lrow >> 5, u = lrow & 31;
        int grow = q * 256 + rank * 32 + u;
        float4 w = *reinterpret_cast<const float4*>(&Whh[(size_t)grow * 256 + k4 * 4]);
        Ws[(k4 * 4 + 0) * 128 + lrow] = w.x;
        Ws[(k4 * 4 + 1) * 128 + lrow] = w.y;
        Ws[(k4 * 4 + 2) * 128 + lrow] = w.z;
        Ws[(k4 * 4 + 3) * 128 + lrow] = w.w;
    }
    __syncthreads();
    CLUSTER_SYNC_();   // all SMEM ready before any DSMEM pushes

    // GEMM roles: s = k-slice (8 x 32k), rowg = 4-row group (32)
    int s    = tid >> 5;
    int rowg = tid & 31;
    // cell roles (tid < 128): b_cell 0..3, u_cell 0..31
    int b_cell = tid >> 5;
    int u_cell = tid & 31;
    int j_cell = rank * 32 + u_cell;

    uint32_t hs0_a = smem_u32(hs0);
    uint32_t hs1_a = smem_u32(hs1);

    const float4* W4 = reinterpret_cast<const float4*>(Ws);
    float4* P4 = reinterpret_cast<float4*>(pbuf);
    float* stg = reinterpret_cast<float*>(stg4);

    float c_state = 0.f;
    bool cellth = tid < 128;
    int ob = cellth ? perm_s[b_cell] : 0;

    // ---- prologue: prefetch xp gate values for t = 0 (all batches have L >= 1) ----
    bool act = cellth;
    float xg0 = 0.f, xg1 = 0.f, xg2 = 0.f, xg3 = 0.f;
    if (cellth) {
        size_t xb = (size_t)ob * TT * GG + (size_t)rank * 32 + u_cell;
        xg0 = xp[xb];
        xg1 = xp[xb + 256];
        xg2 = xp[xb + 512];
        xg3 = xp[xb + 768];
    }

    for (int t = 0; t < Lmax; t++) {
        int pr = t & 1;
        const ulonglong2* H2 = reinterpret_cast<const ulonglong2*>(pr ? hs1 : hs0);
        uint32_t hsw_a = pr ? hs0_a : hs1_a;   // write opposite parity

        // ---- issue prefetch for step t+1 (hidden under GEMM + barrier) ----
        bool act_n = cellth && (t + 1 < Ls_s[b_cell]);
        float ng0 = 0.f, ng1 = 0.f, ng2 = 0.f, ng3 = 0.f;
        if (act_n) {
            size_t xb = ((size_t)ob * TT + (t + 1)) * GG + (size_t)rank * 32 + u_cell;
            ng0 = xp[xb];
            ng1 = xp[xb + 256];
            ng2 = xp[xb + 512];
            ng3 = xp[xb + 768];
        }

        // ---- micro-GEMM over k-slice s (32 k), rows rowg*4..+4, all 4 batches ----
        if (t > 0) {
            ull acc2[4][2];
#pragma unroll
            for (int i = 0; i < 4; i++) { acc2[i][0] = 0ull; acc2[i][1] = 0ull; }
            int kbase = s * 32;
#pragma unroll 8
            for (int k = 0; k < 32; k++) {
                float4 wv = W4[(kbase + k) * 32 + rowg];
                ulonglong2 hp = H2[kbase + k];   // same LDS128, pre-paired f32x2
                ull h01 = hp.x;
                ull h23 = hp.y;
                ull w;
                w = dup_f32(wv.x); ffma2(acc2[0][0], w, h01); ffma2(acc2[0][1], w, h23);
                w = dup_f32(wv.y); ffma2(acc2[1][0], w, h01); ffma2(acc2[1][1], w, h23);
                w = dup_f32(wv.z); ffma2(acc2[2][0], w, h01); ffma2(acc2[2][1], w, h23);
                w = dup_f32(wv.w); ffma2(acc2[3][0], w, h01); ffma2(acc2[3][1], w, h23);
            }
#pragma unroll
            for (int i = 0; i < 4; i++) {
                float2 p0 = unpack_f32(acc2[i][0]);
                float2 p1 = unpack_f32(acc2[i][1]);
                float4 v; v.x = p0.x; v.y = p0.y; v.z = p1.x; v.w = p1.y;
                P4[s * 128 + rowg * 4 + i] = v;
            }
        }
        __syncthreads();

        // ---- reduce 8 k-slices + cell update -> staging buffer + out ----
        if (act) {
            float g0 = xg0, g1 = xg1, g2 = xg2, g3 = xg3;
            if (t > 0) {
#pragma unroll
                for (int s2 = 0; s2 < 8; s2++) {
                    const float* pb = &pbuf[(size_t)(s2 * 128) * 4 + b_cell];
                    g0 += pb[(0 * 32 + u_cell) * 4];
                    g1 += pb[(1 * 32 + u_cell) * 4];
                    g2 += pb[(2 * 32 + u_cell) * 4];
                    g3 += pb[(3 * 32 + u_cell) * 4];
                }
            }
            float i_ = 1.f / (1.f + __expf(-g0));
            float f_ = 1.f / (1.f + __expf(-g1));
            float o_ = 1.f / (1.f + __expf(-g3));
            c_state = f_ * c_state + i_ * tanhf(g2);
            float hv = o_ * tanhf(c_state);

            stg[u_cell * 4 + b_cell] = hv;
            out[((size_t)ob * TT + t) * HH + j_cell] = hv;
        }
        __syncthreads();   // staging complete (finished batches keep frozen h)

        // ---- push: one float4 per thread; 8 ranks x 32 rows of 16B (contiguous) ----
        {
            uint32_t prank = (uint32_t)(tid >> 5);
            int pu = tid & 31;
            float4 v = stg4[pu];
            st_cluster_v4(hsw_a + (uint32_t)((rank * 32 + pu) * 16), prank, v);
        }

        xg0 = ng0; xg1 = ng1; xg2 = ng2; xg3 = ng3;
        act = act_n;

        // ---- one hardware cluster barrier per step ----
        CLUSTER_SYNC_();
    }
}

// ---------------- kernel 3: logits (compacted: one block per live (b,t) row) -----------
__global__ __launch_bounds__(256)
void logits_kernel(const int* __restrict__ seq_len,
                   const float* __restrict__ W_fc)
{
    int m = blockIdx.x;
    if (m >= g_nrows) return;
    int pk = g_rows[m];
    int b = pk >> 16, t = pk & 0xFFFF;
    int L = seq_len[b];
    int bt = b * TT + t;

    __shared__ float outs[2 * HH];
    __shared__ float dots[CC];
    __shared__ float lse_s;

    int tid = threadIdx.x;  // 256
    outs[tid]       = g_out_f[(size_t)bt * HH + tid];
    outs[HH + tid]  = g_out_b[(size_t)(b * TT + (L - 1 - t)) * HH + tid];
    __syncthreads();

    int warp = tid >> 5, lane = tid & 31;
    for (int cls = warp; cls < CC; cls += 8) {
        float acc = 0.f;
#pragma unroll 4
        for (int e = lane; e < 2 * HH; e += 32)
            acc += outs[e] * W_fc[cls * (2 * HH) + e];
#pragma unroll
        for (int off = 16; off; off >>= 1)
            acc += __shfl_down_sync(0xffffffffu, acc, off);
        if (lane == 0) dots[cls] = acc;
    }
    __syncthreads();

    if (tid == 0) {
        float m2 = -INFINITY;
        for (int cI = 0; cI < CC; cI++) m2 = fmaxf(m2, dots[cI]);
        float sum = 0.f;
        for (int cI = 0; cI < CC; cI++) sum += expf(dots[cI] - m2);
        lse_s = m2 + logf(sum);
    }
    __syncthreads();

    if (tid < CC) g_logits[(size_t)bt * CC + tid] = dots[tid] - lse_s;
}

// ---------------- kernel 4: CRF gold score + forward algorithm, warp per batch ----------
__global__ __launch_bounds__(32)
void crf_kernel(const int* __restrict__ seq_len, const int* __restrict__ y,
                const float* __restrict__ start_t, const float* __restrict__ end_t,
                const float* __restrict__ trans)
{
    int b = blockIdx.x;
    int lane = threadIdx.x;  // 32

    __shared__ float trans_s[CC * CC];
    __shared__ float alpha_s[CC];
    for (int i = lane; i < CC * CC; i += 32) trans_s[i] = trans[i];
    __syncwarp();

    int L = seq_len[b];
    const float* lg = g_logits + (size_t)b * TT * CC;
    const int* yb = y + b * TT;

    float part = 0.f;
    for (int t = 1 + lane; t < L; t += 32)
        part += trans_s[yb[t - 1] * CC + yb[t]] + lg[t * CC + yb[t]];
#pragma unroll
    for (int off = 16; off; off >>= 1)
        part += __shfl_down_sync(0xffffffffu, part, off);

    float score = 0.f;
    if (lane == 0)
        score = part + start_t[yb[0]] + lg[yb[0]] + end_t[yb[L - 1]];

    int j = lane;
    float alpha = (j < CC) ? (start_t[j] + lg[j]) : -INFINITY;
    for (int t = 1; t < L; t++) {
        if (j < CC) alpha_s[j] = alpha;
        __syncwarp();
        float na = alpha;
        if (j < CC) {
            float m = -INFINITY;
#pragma unroll
            for (int i = 0; i < CC; i++)
                m = fmaxf(m, alpha_s[i] + trans_s[i * CC + j]);
            float sum = 0.f;
#pragma unroll
            for (int i = 0; i < CC; i++)
                sum += expf(alpha_s[i] + trans_s[i * CC + j] - m);
            na = m + logf(sum) + lg[t * CC + j];
        }
        __syncwarp();
        alpha = na;
    }

    if (j < CC) alpha_s[j] = alpha + end_t[j];
    __syncwarp();
    if (lane == 0) {
        float m = -INFINITY;
        for (int i = 0; i < CC; i++) m = fmaxf(m, alpha_s[i]);
        float sum = 0.f;
        for (int i = 0; i < CC; i++) sum += expf(alpha_s[i] - m);
        float logZ = m + logf(sum);
        g_llh[b] = score - logZ;
    }
}

// ---------------- kernel 5: loss = -sum_b llh[b] ----------------
__global__ __launch_bounds__(32)
void finalize_kernel(float* __restrict__ out)
{
    int lane = threadIdx.x;
    float v = g_llh[lane];
#pragma unroll
    for (int off = 16; off; off >>= 1)
        v += __shfl_down_sync(0xffffffffu, v, off);
    if (lane == 0) out[0] = -v;
}

// ---------------- launch ----------------
extern "C" void kernel_launch(void* const* d_in, const int* in_sizes, int n_in,
                              void* d_out, int out_size)
{
    (void)in_sizes; (void)n_in; (void)out_size;
    const int*   x       = (const int*)  d_in[0];
    const int*   seq_len = (const int*)  d_in[1];
    const int*   y       = (const int*)  d_in[2];
    // d_in[3] = mask (derived from seq_len instead)
    const float* emb     = (const float*)d_in[4];
    const float* Wih_f   = (const float*)d_in[5];
    const float* Whh_f   = (const float*)d_in[6];
    const float* b_f     = (const float*)d_in[7];
    const float* Wih_b   = (const float*)d_in[8];
    const float* Whh_b   = (const float*)d_in[9];
    const float* b_b     = (const float*)d_in[10];
    const float* W_fc    = (const float*)d_in[11];
    const float* start_t = (const float*)d_in[12];
    const float* end_t   = (const float*)d_in[13];
    const float* trans   = (const float*)d_in[14];
    float* out = (float*)d_out;

    // scan dynamic SMEM: Ws 128KB + hs 2x4KB + pbuf 16KB = 152KB
    const int scan_smem = (256 * 128 + 2 * 256 * 4 + 8 * 128 * 4) * (int)sizeof(float);
    static int smem_set = 0;
    if (!smem_set) {
        cudaFuncSetAttribute(lstm_scan4,
                             cudaFuncAttributeMaxDynamicSharedMemorySize, scan_smem);
        smem_set = 1;
    }

    setup_kernel<<<1, 256>>>(seq_len);

    dim3 ggrid(GG / 128, MM / 128);
    gemm_xp<<<ggrid, 256>>>(x, seq_len, emb, Wih_f, b_f, 0);
    gemm_xp<<<ggrid, 256>>>(x, seq_len, emb, Wih_b, b_b, 1);

    lstm_scan4<<<128, 256, scan_smem>>>(Whh_f, Whh_b);

    logits_kernel<<<MM, 256>>>(seq_len, W_fc);

    crf_kernel<<<BB, 32>>>(seq_len, y, start_t, end_t, trans);

    finalize_kernel<<<1, 32>>>(out);
}

// round 17
// speedup vs baseline: 1.5317x; 1.0090x over previous
#include <cuda_runtime.h>
#include <math.h>
#include <stdint.h>

// Problem constants
#define BB 32
#define TT 512
#define EE 256
#define HH 256
#define GG 1024          // 4*H
#define CC 20
#define MM (BB * TT)     // 16384

typedef unsigned long long ull;

// ---------------- f32x2 packed helpers (Blackwell) ----------------
__device__ __forceinline__ ull dup_f32(float x) {
    ull r;
    asm("mov.b64 %0, {%1, %1};" : "=l"(r) : "f"(x));
    return r;
}
__device__ __forceinline__ void ffma2(ull& acc, ull a, ull b) {
    asm("fma.rn.f32x2 %0, %1, %2, %0;" : "+l"(acc) : "l"(a), "l"(b));
}
__device__ __forceinline__ float2 unpack_f32(ull v) {
    float lo, hi;
    asm("mov.b64 {%0, %1}, %2;" : "=f"(lo), "=f"(hi) : "l"(v));
    return make_float2(lo, hi);
}

// ---------------- tf32 mma helpers ----------------
__device__ __forceinline__ uint32_t to_tf32(float v) {
    uint32_t r;
    asm("cvt.rna.tf32.f32 %0, %1;" : "=r"(r) : "f"(v));
    return r;
}
__device__ __forceinline__ void mma_tf32(float* d, const uint32_t* a,
                                         uint32_t b0, uint32_t b1) {
    asm volatile(
        "mma.sync.aligned.m16n8k8.row.col.f32.tf32.tf32.f32 "
        "{%0,%1,%2,%3}, {%4,%5,%6,%7}, {%8,%9}, {%0,%1,%2,%3};"
        : "+f"(d[0]), "+f"(d[1]), "+f"(d[2]), "+f"(d[3])
        : "r"(a[0]), "r"(a[1]), "r"(a[2]), "r"(a[3]), "r"(b0), "r"(b1));
}

// ---------------- cluster / DSMEM helpers ----------------
__device__ __forceinline__ uint32_t smem_u32(const void* p) {
    uint32_t a;
    asm("{ .reg .u64 t; cvta.to.shared.u64 t, %1; cvt.u32.u64 %0, t; }"
        : "=r"(a) : "l"(p));
    return a;
}
__device__ __forceinline__ void st_cluster_v4(uint32_t local_addr, uint32_t rank, float4 v) {
    uint32_t ra;
    asm("mapa.shared::cluster.u32 %0, %1, %2;" : "=r"(ra) : "r"(local_addr), "r"(rank));
    asm volatile("st.shared::cluster.v4.f32 [%0], {%1, %2, %3, %4};"
                 :: "r"(ra), "f"(v.x), "f"(v.y), "f"(v.z), "f"(v.w) : "memory");
}
#define CLUSTER_SYNC_() do { \
    asm volatile("barrier.cluster.arrive.aligned;" ::: "memory"); \
    asm volatile("barrier.cluster.wait.aligned;" ::: "memory"); } while (0)

// ---------------- device scratch (allocation-free rule: static __device__) --------------
__device__ float g_xp_f[(size_t)MM * GG];   // 64 MB
__device__ float g_xp_b[(size_t)MM * GG];   // 64 MB
__device__ float g_out_f[(size_t)MM * HH];  // 16 MB
__device__ float g_out_b[(size_t)MM * HH];  // 16 MB
__device__ float g_logits[(size_t)MM * CC];
__device__ float g_llh[BB];

// scan bookkeeping
__device__ int g_perm[BB];                  // sorted(batch) -> original batch
__device__ int g_Lsorted[BB];               // lengths, descending

// GEMM compaction
__device__ int g_rows[MM];                  // packed (b<<16)|t for t < seq_len[b]
__device__ int g_nrows;

// ---------------- kernel 0: setup ----------------
__global__ __launch_bounds__(256)
void setup_kernel(const int* __restrict__ seq_len)
{
    __shared__ int off_s[BB + 1];
    int tid = threadIdx.x;

    if (tid == 0) {
        int L[BB], p[BB];
        for (int i = 0; i < BB; i++) { L[i] = seq_len[i]; p[i] = i; }
        // stable insertion sort, descending by L
        for (int i = 1; i < BB; i++) {
            int kl = L[i], kp = p[i];
            int j = i - 1;
            while (j >= 0 && L[j] < kl) { L[j + 1] = L[j]; p[j + 1] = p[j]; j--; }
            L[j + 1] = kl; p[j + 1] = kp;
        }
        for (int i = 0; i < BB; i++) { g_perm[i] = p[i]; g_Lsorted[i] = L[i]; }
        // prefix offsets in ORIGINAL batch order for row compaction
        int off = 0;
        for (int b = 0; b < BB; b++) { off_s[b] = off; off += seq_len[b]; }
        off_s[BB] = off;
        g_nrows = off;
    }
    __syncthreads();

    // fill compacted row list: thread group (b, r) writes rows t = r, r+8, ...
    int b = tid >> 3, r = tid & 7;
    int off = off_s[b];
    int L = off_s[b + 1] - off;
    for (int t = r; t < L; t += 8)
        g_rows[off + t] = (b << 16) | t;
}

// ---------------- kernel 1: xp = gather(emb, x[, reversed]) @ Wih^T + bias -------------
// Both directions in ONE launch (blockIdx.z = rev). Compacted M. Tile 128x128, BK=16,
// 256 threads, tf32 mma.sync (m16n8k8), 2-stage SMEM double buffer with register
// prefetch: one __syncthreads per chunk, LDG latency hidden under mma compute.
__global__ __launch_bounds__(256)
void gemm_xp(const int* __restrict__ x, const int* __restrict__ seq_len,
             const float* __restrict__ emb,
             const float* __restrict__ Wih_f, const float* __restrict__ b_f,
             const float* __restrict__ Wih_b, const float* __restrict__ b_b)
{
    const int BM = 128, BN = 128, BK = 16, NCH = EE / BK;   // 16 chunks
    const int LDA = BK + 4;                                  // stride 20: conflict-free frags
    __shared__ float As[2][BM][LDA];
    __shared__ float Bs[2][BN][LDA];
    __shared__ int tok[BM];
    __shared__ int orow[BM];

    int nrows = g_nrows;
    int m0 = blockIdx.y * BM;
    if (m0 >= nrows) return;

    int rev = blockIdx.z;
    const float* __restrict__ Wih  = rev ? Wih_b : Wih_f;
    const float* __restrict__ bias = rev ? b_b   : b_f;
    float* __restrict__ xp         = rev ? g_xp_b : g_xp_f;

    int tid = threadIdx.x;                 // 256
    int n0 = blockIdx.x * BN;

    if (tid < BM) {
        int m = m0 + tid;
        if (m < nrows) {
            int pk = g_rows[m];
            int b = pk >> 16, t = pk & 0xFFFF;
            int tp = rev ? (seq_len[b] - 1 - t) : t;   // t < L by construction
            tok[tid]  = x[b * TT + tp];
            orow[tid] = b * TT + t;
        } else {
            tok[tid] = 0;
            orow[tid] = -1;
        }
    }
    __syncthreads();

    // staging roles: thread -> row ar, k-half ac (8 floats = 2 float4)
    int ar = tid >> 1, ac = (tid & 1) * 8;
    const float* a_src = &emb[(size_t)tok[ar] * EE + ac];
    const float* b_src = &Wih[(size_t)(n0 + ar) * EE + ac];

    // fragment roles
    int wid  = tid >> 5, lane = tid & 31;
    int warpM = wid & 3;        // 4 m-warps of 32 rows
    int warpN = wid >> 2;       // 2 n-warps of 64 cols
    int gID = lane >> 2, tig = lane & 3;

    float d[2][8][4];
#pragma unroll
    for (int mt = 0; mt < 2; mt++)
#pragma unroll
        for (int nt = 0; nt < 8; nt++)
#pragma unroll
            for (int e = 0; e < 4; e++) d[mt][nt][e] = 0.f;

    // ---- prologue: chunk 0 -> buffer 0 ----
    float4 av0 = *reinterpret_cast<const float4*>(a_src);
    float4 av1 = *reinterpret_cast<const float4*>(a_src + 4);
    float4 bv0 = *reinterpret_cast<const float4*>(b_src);
    float4 bv1 = *reinterpret_cast<const float4*>(b_src + 4);
    As[0][ar][ac + 0] = av0.x; As[0][ar][ac + 1] = av0.y;
    As[0][ar][ac + 2] = av0.z; As[0][ar][ac + 3] = av0.w;
    As[0][ar][ac + 4] = av1.x; As[0][ar][ac + 5] = av1.y;
    As[0][ar][ac + 6] = av1.z; As[0][ar][ac + 7] = av1.w;
    Bs[0][ar][ac + 0] = bv0.x; Bs[0][ar][ac + 1] = bv0.y;
    Bs[0][ar][ac + 2] = bv0.z; Bs[0][ar][ac + 3] = bv0.w;
    Bs[0][ar][ac + 4] = bv1.x; Bs[0][ar][ac + 5] = bv1.y;
    Bs[0][ar][ac + 6] = bv1.z; Bs[0][ar][ac + 7] = bv1.w;
    __syncthreads();

    for (int ch = 0; ch < NCH; ch++) {
        int buf = ch & 1;

        // issue LDG for chunk ch+1 (latency hidden under this chunk's mma)
        if (ch + 1 < NCH) {
            int k0 = (ch + 1) * BK;
            av0 = *reinterpret_cast<const float4*>(a_src + k0);
            av1 = *reinterpret_cast<const float4*>(a_src + k0 + 4);
            bv0 = *reinterpret_cast<const float4*>(b_src + k0);
            bv1 = *reinterpret_cast<const float4*>(b_src + k0 + 4);
        }

#pragma unroll
        for (int ks = 0; ks < 2; ks++) {
            int kb = ks * 8;
            uint32_t at[2][4];
#pragma unroll
            for (int mt = 0; mt < 2; mt++) {
                int r = warpM * 32 + mt * 16 + gID;
                at[mt][0] = to_tf32(As[buf][r    ][kb + tig    ]);
                at[mt][1] = to_tf32(As[buf][r + 8][kb + tig    ]);
                at[mt][2] = to_tf32(As[buf][r    ][kb + tig + 4]);
                at[mt][3] = to_tf32(As[buf][r + 8][kb + tig + 4]);
            }
#pragma unroll
            for (int nt = 0; nt < 8; nt++) {
                int n = warpN * 64 + nt * 8 + gID;
                uint32_t b0 = to_tf32(Bs[buf][n][kb + tig    ]);
                uint32_t b1 = to_tf32(Bs[buf][n][kb + tig + 4]);
                mma_tf32(d[0][nt], at[0], b0, b1);
                mma_tf32(d[1][nt], at[1], b0, b1);
            }
        }

        if (ch + 1 < NCH) {
            int nb = buf ^ 1;
            As[nb][ar][ac + 0] = av0.x; As[nb][ar][ac + 1] = av0.y;
            As[nb][ar][ac + 2] = av0.z; As[nb][ar][ac + 3] = av0.w;
            As[nb][ar][ac + 4] = av1.x; As[nb][ar][ac + 5] = av1.y;
            As[nb][ar][ac + 6] = av1.z; As[nb][ar][ac + 7] = av1.w;
            Bs[nb][ar][ac + 0] = bv0.x; Bs[nb][ar][ac + 1] = bv0.y;
            Bs[nb][ar][ac + 2] = bv0.z; Bs[nb][ar][ac + 3] = bv0.w;
            Bs[nb][ar][ac + 4] = bv1.x; Bs[nb][ar][ac + 5] = bv1.y;
            Bs[nb][ar][ac + 6] = bv1.z; Bs[nb][ar][ac + 7] = bv1.w;
            __syncthreads();
        }
    }

    // epilogue: bias + scattered float2 stores per fragment
#pragma unroll
    for (int mt = 0; mt < 2; mt++) {
        int r0 = warpM * 32 + mt * 16 + gID;
#pragma unroll
        for (int nt = 0; nt < 8; nt++) {
            int n = n0 + warpN * 64 + nt * 8 + tig * 2;
            float bj0 = bias[n], bj1 = bias[n + 1];
            int om = orow[r0];
            if (om >= 0) {
                float2 v; v.x = d[mt][nt][0] + bj0; v.y = d[mt][nt][1] + bj1;
                *reinterpret_cast<float2*>(&xp[(size_t)om * GG + n]) = v;
            }
            int om2 = orow[r0 + 8];
            if (om2 >= 0) {
                float2 v; v.x = d[mt][nt][2] + bj0; v.y = d[mt][nt][3] + bj1;
                *reinterpret_cast<float2*>(&xp[(size_t)om2 * GG + n]) = v;
            }
        }
    }
}

// ---------------- kernel 2: clustered LSTM scan (R14/R16, frozen) ----------------------
// 128 CTAs = 16 clusters x 8. cluster cid: dir = cid&1, grp = cid>>1 (4 sorted batches).
// CTA rank owns hidden units [rank*32, rank*32+32) -> 128 gate rows of Whh (128KB) in
// SMEM for the whole scan. Per step: 128row x 4batch x 256k micro-GEMM from SMEM,
// cell update into a staging buffer, ONE float4 remote store per thread, ONE hardware
// cluster barrier. xp loads are software double-buffered one step ahead.
__global__ __launch_bounds__(256) __cluster_dims__(8, 1, 1)
void lstm_scan4(const float* __restrict__ Whh_f, const float* __restrict__ Whh_b)
{
    extern __shared__ float sm[];
    float* Ws   = sm;                       // [256][128]  Ws[k*128 + lrow], lrow = q*32+u
    float* hs0  = sm + 256 * 128;           // [256][4]    h buffer parity 0
    float* hs1  = hs0 + 256 * 4;            // [256][4]    h buffer parity 1
    float* pbuf = hs1 + 256 * 4;            // [8][128][4] pbuf[(s*128+row)*4 + b]

    __shared__ float4 stg4[32];             // staged h: stg4[u] = (b0,b1,b2,b3)
    __shared__ int perm_s[4];
    __shared__ int Ls_s[4];

    int bid  = blockIdx.x;
    int cid  = bid >> 3;
    int rank = bid & 7;
    int dir  = cid & 1;
    int grp  = cid >> 1;
    int tid  = threadIdx.x;

    const float* __restrict__ xp  = dir ? g_xp_b : g_xp_f;
    const float* __restrict__ Whh = dir ? Whh_b : Whh_f;
    float* __restrict__ out       = dir ? g_out_b : g_out_f;

    if (tid < 4) {
        perm_s[tid] = g_perm[grp * 4 + tid];
        Ls_s[tid]   = g_Lsorted[grp * 4 + tid];
    }
    int Lmax = g_Lsorted[grp * 4];          // group sorted desc -> first is longest

    // ---- load this CTA's 128 gate rows of Whh into SMEM, k-major ----
    for (int i = tid; i < 128 * 64; i += 256) {
        int lrow = i & 127, k4 = i >> 7;
        int q = lrow >> 5, u = lrow & 31;
        int grow = q * 256 + rank * 32 + u;
        float4 w = *reinterpret_cast<const float4*>(&Whh[(size_t)grow * 256 + k4 * 4]);
        Ws[(k4 * 4 + 0) * 128 + lrow] = w.x;
        Ws[(k4 * 4 + 1) * 128 + lrow] = w.y;
        Ws[(k4 * 4 + 2) * 128 + lrow] = w.z;
        Ws[(k4 * 4 + 3) * 128 + lrow] = w.w;
    }
    __syncthreads();
    CLUSTER_SYNC_();   // all SMEM ready before any DSMEM pushes

    // GEMM roles: s = k-slice (8 x 32k), rowg = 4-row group (32)
    int s    = tid >> 5;
    int rowg = tid & 31;
    // cell roles (tid < 128): b_cell 0..3, u_cell 0..31
    int b_cell = tid >> 5;
    int u_cell = tid & 31;
    int j_cell = rank * 32 + u_cell;

    uint32_t hs0_a = smem_u32(hs0);
    uint32_t hs1_a = smem_u32(hs1);

    const float4* W4 = reinterpret_cast<const float4*>(Ws);
    float4* P4 = reinterpret_cast<float4*>(pbuf);
    float* stg = reinterpret_cast<float*>(stg4);

    float c_state = 0.f;
    bool cellth = tid < 128;
    int ob = cellth ? perm_s[b_cell] : 0;

    // ---- prologue: prefetch xp gate values for t = 0 (all batches have L >= 1) ----
    bool act = cellth;
    float xg0 = 0.f, xg1 = 0.f, xg2 = 0.f, xg3 = 0.f;
    if (cellth) {
        size_t xb = (size_t)ob * TT * GG + (size_t)rank * 32 + u_cell;
        xg0 = xp[xb];
        xg1 = xp[xb + 256];
        xg2 = xp[xb + 512];
        xg3 = xp[xb + 768];
    }

    for (int t = 0; t < Lmax; t++) {
        int pr = t & 1;
        const ulonglong2* H2 = reinterpret_cast<const ulonglong2*>(pr ? hs1 : hs0);
        uint32_t hsw_a = pr ? hs0_a : hs1_a;   // write opposite parity

        // ---- issue prefetch for step t+1 (hidden under GEMM + barrier) ----
        bool act_n = cellth && (t + 1 < Ls_s[b_cell]);
        float ng0 = 0.f, ng1 = 0.f, ng2 = 0.f, ng3 = 0.f;
        if (act_n) {
            size_t xb = ((size_t)ob * TT + (t + 1)) * GG + (size_t)rank * 32 + u_cell;
            ng0 = xp[xb];
            ng1 = xp[xb + 256];
            ng2 = xp[xb + 512];
            ng3 = xp[xb + 768];
        }

        // ---- micro-GEMM over k-slice s (32 k), rows rowg*4..+4, all 4 batches ----
        if (t > 0) {
            ull acc2[4][2];
#pragma unroll
            for (int i = 0; i < 4; i++) { acc2[i][0] = 0ull; acc2[i][1] = 0ull; }
            int kbase = s * 32;
#pragma unroll 8
            for (int k = 0; k < 32; k++) {
                float4 wv = W4[(kbase + k) * 32 + rowg];
                ulonglong2 hp = H2[kbase + k];   // same LDS128, pre-paired f32x2
                ull h01 = hp.x;
                ull h23 = hp.y;
                ull w;
                w = dup_f32(wv.x); ffma2(acc2[0][0], w, h01); ffma2(acc2[0][1], w, h23);
                w = dup_f32(wv.y); ffma2(acc2[1][0], w, h01); ffma2(acc2[1][1], w, h23);
                w = dup_f32(wv.z); ffma2(acc2[2][0], w, h01); ffma2(acc2[2][1], w, h23);
                w = dup_f32(wv.w); ffma2(acc2[3][0], w, h01); ffma2(acc2[3][1], w, h23);
            }
#pragma unroll
            for (int i = 0; i < 4; i++) {
                float2 p0 = unpack_f32(acc2[i][0]);
                float2 p1 = unpack_f32(acc2[i][1]);
                float4 v; v.x = p0.x; v.y = p0.y; v.z = p1.x; v.w = p1.y;
                P4[s * 128 + rowg * 4 + i] = v;
            }
        }
        __syncthreads();

        // ---- reduce 8 k-slices + cell update -> staging buffer + out ----
        if (act) {
            float g0 = xg0, g1 = xg1, g2 = xg2, g3 = xg3;
            if (t > 0) {
#pragma unroll
                for (int s2 = 0; s2 < 8; s2++) {
                    const float* pb = &pbuf[(size_t)(s2 * 128) * 4 + b_cell];
                    g0 += pb[(0 * 32 + u_cell) * 4];
                    g1 += pb[(1 * 32 + u_cell) * 4];
                    g2 += pb[(2 * 32 + u_cell) * 4];
                    g3 += pb[(3 * 32 + u_cell) * 4];
                }
            }
            float i_ = 1.f / (1.f + __expf(-g0));
            float f_ = 1.f / (1.f + __expf(-g1));
            float o_ = 1.f / (1.f + __expf(-g3));
            c_state = f_ * c_state + i_ * tanhf(g2);
            float hv = o_ * tanhf(c_state);

            stg[u_cell * 4 + b_cell] = hv;
            out[((size_t)ob * TT + t) * HH + j_cell] = hv;
        }
        __syncthreads();   // staging complete (finished batches keep frozen h)

        // ---- push: one float4 per thread; 8 ranks x 32 rows of 16B (contiguous) ----
        {
            uint32_t prank = (uint32_t)(tid >> 5);
            int pu = tid & 31;
            float4 v = stg4[pu];
            st_cluster_v4(hsw_a + (uint32_t)((rank * 32 + pu) * 16), prank, v);
        }

        xg0 = ng0; xg1 = ng1; xg2 = ng2; xg3 = ng3;
        act = act_n;

        // ---- one hardware cluster barrier per step ----
        CLUSTER_SYNC_();
    }
}

// ---------------- kernel 3: logits (compacted: one block per live (b,t) row) -----------
__global__ __launch_bounds__(256)
void logits_kernel(const int* __restrict__ seq_len,
                   const float* __restrict__ W_fc)
{
    int m = blockIdx.x;
    if (m >= g_nrows) return;
    int pk = g_rows[m];
    int b = pk >> 16, t = pk & 0xFFFF;
    int L = seq_len[b];
    int bt = b * TT + t;

    __shared__ float outs[2 * HH];
    __shared__ float dots[CC];
    __shared__ float lse_s;

    int tid = threadIdx.x;  // 256
    outs[tid]       = g_out_f[(size_t)bt * HH + tid];
    outs[HH + tid]  = g_out_b[(size_t)(b * TT + (L - 1 - t)) * HH + tid];
    __syncthreads();

    int warp = tid >> 5, lane = tid & 31;
    for (int cls = warp; cls < CC; cls += 8) {
        float acc = 0.f;
#pragma unroll 4
        for (int e = lane; e < 2 * HH; e += 32)
            acc += outs[e] * W_fc[cls * (2 * HH) + e];
#pragma unroll
        for (int off = 16; off; off >>= 1)
            acc += __shfl_down_sync(0xffffffffu, acc, off);
        if (lane == 0) dots[cls] = acc;
    }
    __syncthreads();

    if (tid == 0) {
        float m2 = -INFINITY;
        for (int cI = 0; cI < CC; cI++) m2 = fmaxf(m2, dots[cI]);
        float sum = 0.f;
        for (int cI = 0; cI < CC; cI++) sum += expf(dots[cI] - m2);
        lse_s = m2 + logf(sum);
    }
    __syncthreads();

    if (tid < CC) g_logits[(size_t)bt * CC + tid] = dots[tid] - lse_s;
}

// ---------------- kernel 4: CRF gold score + forward algorithm, warp per batch ----------
__global__ __launch_bounds__(32)
void crf_kernel(const int* __restrict__ seq_len, const int* __restrict__ y,
                const float* __restrict__ start_t, const float* __restrict__ end_t,
                const float* __restrict__ trans)
{
    int b = blockIdx.x;
    int lane = threadIdx.x;  // 32

    __shared__ float trans_s[CC * CC];
    __shared__ float alpha_s[CC];
    for (int i = lane; i < CC * CC; i += 32) trans_s[i] = trans[i];
    __syncwarp();

    int L = seq_len[b];
    const float* lg = g_logits + (size_t)b * TT * CC;
    const int* yb = y + b * TT;

    float part = 0.f;
    for (int t = 1 + lane; t < L; t += 32)
        part += trans_s[yb[t - 1] * CC + yb[t]] + lg[t * CC + yb[t]];
#pragma unroll
    for (int off = 16; off; off >>= 1)
        part += __shfl_down_sync(0xffffffffu, part, off);

    float score = 0.f;
    if (lane == 0)
        score = part + start_t[yb[0]] + lg[yb[0]] + end_t[yb[L - 1]];

    int j = lane;
    float alpha = (j < CC) ? (start_t[j] + lg[j]) : -INFINITY;
    for (int t = 1; t < L; t++) {
        if (j < CC) alpha_s[j] = alpha;
        __syncwarp();
        float na = alpha;
        if (j < CC) {
            float m = -INFINITY;
#pragma unroll
            for (int i = 0; i < CC; i++)
                m = fmaxf(m, alpha_s[i] + trans_s[i * CC + j]);
            float sum = 0.f;
#pragma unroll
            for (int i = 0; i < CC; i++)
                sum += expf(alpha_s[i] + trans_s[i * CC + j] - m);
            na = m + logf(sum) + lg[t * CC + j];
        }
        __syncwarp();
        alpha = na;
    }

    if (j < CC) alpha_s[j] = alpha + end_t[j];
    __syncwarp();
    if (lane == 0) {
        float m = -INFINITY;
        for (int i = 0; i < CC; i++) m = fmaxf(m, alpha_s[i]);
        float sum = 0.f;
        for (int i = 0; i < CC; i++) sum += expf(alpha_s[i] - m);
        float logZ = m + logf(sum);
        g_llh[b] = score - logZ;
    }
}

// ---------------- kernel 5: loss = -sum_b llh[b] ----------------
__global__ __launch_bounds__(32)
void finalize_kernel(float* __restrict__ out)
{
    int lane = threadIdx.x;
    float v = g_llh[lane];
#pragma unroll
    for (int off = 16; off; off >>= 1)
        v += __shfl_down_sync(0xffffffffu, v, off);
    if (lane == 0) out[0] = -v;
}

// ---------------- launch ----------------
extern "C" void kernel_launch(void* const* d_in, const int* in_sizes, int n_in,
                              void* d_out, int out_size)
{
    (void)in_sizes; (void)n_in; (void)out_size;
    const int*   x       = (const int*)  d_in[0];
    const int*   seq_len = (const int*)  d_in[1];
    const int*   y       = (const int*)  d_in[2];
    // d_in[3] = mask (derived from seq_len instead)
    const float* emb     = (const float*)d_in[4];
    const float* Wih_f   = (const float*)d_in[5];
    const float* Whh_f   = (const float*)d_in[6];
    const float* b_f     = (const float*)d_in[7];
    const float* Wih_b   = (const float*)d_in[8];
    const float* Whh_b   = (const float*)d_in[9];
    const float* b_b     = (const float*)d_in[10];
    const float* W_fc    = (const float*)d_in[11];
    const float* start_t = (const float*)d_in[12];
    const float* end_t   = (const float*)d_in[13];
    const float* trans   = (const float*)d_in[14];
    float* out = (float*)d_out;

    // scan dynamic SMEM: Ws 128KB + hs 2x4KB + pbuf 16KB = 152KB
    const int scan_smem = (256 * 128 + 2 * 256 * 4 + 8 * 128 * 4) * (int)sizeof(float);
    static int smem_set = 0;
    if (!smem_set) {
        cudaFuncSetAttribute(lstm_scan4,
                             cudaFuncAttributeMaxDynamicSharedMemorySize, scan_smem);
        smem_set = 1;
    }

    setup_kernel<<<1, 256>>>(seq_len);

    dim3 ggrid(GG / 128, MM / 128, 2);
    gemm_xp<<<ggrid, 256>>>(x, seq_len, emb, Wih_f, b_f, Wih_b, b_b);

    lstm_scan4<<<128, 256, scan_smem>>>(Whh_f, Whh_b);

    logits_kernel<<<MM, 256>>>(seq_len, W_fc);

    crf_kernel<<<BB, 32>>>(seq_len, y, start_t, end_t, trans);

    finalize_kernel<<<1, 32>>>(out);
}